// round 1
// baseline (speedup 1.0000x reference)
#include <cuda_runtime.h>
#include <cstdint>

#define D 128
#define NW 100000
#define NT 10000
#define ND 50000

// ---------------- scratch (device globals: allocation-free) ----------------
__device__ float g_hw[(size_t)NW * D];   // composed-linear word features
__device__ float g_ht[(size_t)NT * D];   // composed-linear topic features
__device__ float g_cnt[NW + NT + NT + ND + ND];  // per-(relation,dst) edge counts
__device__ float g_T1[D * D];
__device__ float g_Bw[D * D];
__device__ float g_Bt[D * D];
__device__ float g_bw[D];
__device__ float g_bt[D];

// ---------------- f32x2 helpers (Blackwell packed fp32 FMA) ----------------
__device__ __forceinline__ unsigned long long fma2(unsigned long long a,
                                                   unsigned long long b,
                                                   unsigned long long c) {
    unsigned long long d;
    asm("fma.rn.f32x2 %0, %1, %2, %3;" : "=l"(d) : "l"(a), "l"(b), "l"(c));
    return d;
}
__device__ __forceinline__ unsigned long long dup2(float x) {
    unsigned long long d;
    asm("mov.b64 %0, {%1, %1};" : "=l"(d) : "f"(x));
    return d;
}

// ---------------- zero outputs + counts ----------------
__global__ void zero_kernel(float4* out4, int n4, float* cnt, int ncnt) {
    int g = blockIdx.x * blockDim.x + threadIdx.x;
    if (g < n4) out4[g] = make_float4(0.f, 0.f, 0.f, 0.f);
    if (g < ncnt) cnt[g] = 0.f;
}

// ---------------- weight composition ----------------
// T1[i][j] = sum_k W_ww[k][i] * W_wt[j][k]        (= (W_ww^T @ W_wt^T)[i][j])
__global__ void compose_T1(const float* __restrict__ Www,
                           const float* __restrict__ Wwt) {
    int i = blockIdx.x, j = threadIdx.x;
    float s = 0.f;
    for (int k = 0; k < D; k++) s += Www[k * D + i] * Wwt[j * D + k];
    g_T1[i * D + j] = s;
}
// Bw[i][j] = sum_k T1[i][k] * W_wd[j][k];  Bt[i][j] = sum_k W_td[k][i] * W_tt[j][k]
__global__ void compose_B(const float* __restrict__ Wwd,
                          const float* __restrict__ Wtd,
                          const float* __restrict__ Wtt) {
    int i = blockIdx.x, j = threadIdx.x;
    float s = 0.f, t = 0.f;
    for (int k = 0; k < D; k++) {
        s += g_T1[i * D + k] * Wwd[j * D + k];
        t += Wtd[k * D + i] * Wtt[j * D + k];
    }
    g_Bw[i * D + j] = s;
    g_Bt[i * D + j] = t;
}
// bias composition
__global__ void compose_bias(const float* __restrict__ bww,
                             const float* __restrict__ Wwt,
                             const float* __restrict__ bwt,
                             const float* __restrict__ Wwd,
                             const float* __restrict__ bwd,
                             const float* __restrict__ btd,
                             const float* __restrict__ Wtt,
                             const float* __restrict__ btt) {
    __shared__ float tb1[D];
    int j = threadIdx.x;
    float tb = bwt[j];
    for (int m = 0; m < D; m++) tb += bww[m] * Wwt[j * D + m];
    tb1[j] = tb;
    __syncthreads();
    float s = bwd[j];
    for (int k = 0; k < D; k++) s += tb1[k] * Wwd[j * D + k];
    g_bw[j] = s;
    float t = btt[j];
    for (int k = 0; k < D; k++) t += btd[k] * Wtt[j * D + k];
    g_bt[j] = t;
}

// ---------------- GEMM: C[M,128] = A[M,128] @ B[128,128] + bias ----------------
// 64-row blocks, 128 threads, 8x8 register tile per thread, f32x2 FMAs.
__global__ void __launch_bounds__(128, 2)
gemm128(const float* __restrict__ A, int M, const float* __restrict__ B,
        const float* __restrict__ bias, float* __restrict__ C) {
    extern __shared__ float smem[];
    float* Bs = smem;            // 128*128 floats = 64KB
    float* As = smem + D * D;    // 64*128 floats  = 32KB
    const int tid = threadIdx.x;
    const int row0 = blockIdx.x * 64;

    // load B (16384 floats / 128 threads = 32 float4 each)
    {
        const float4* B4 = (const float4*)B;
        float4* Bs4 = (float4*)Bs;
#pragma unroll
        for (int i = 0; i < 32; i++) Bs4[tid + 128 * i] = B4[tid + 128 * i];
    }
    // load A tile (64 rows x 128 = 2048 float4 / 128 threads = 16 each)
    {
        const float4* A4 = (const float4*)A;
        float4* As4 = (float4*)As;
#pragma unroll
        for (int i = 0; i < 16; i++) {
            int idx = tid + 128 * i;     // 0..2047
            int r = idx >> 5, c = idx & 31;
            float4 v = make_float4(0.f, 0.f, 0.f, 0.f);
            if (row0 + r < M) v = A4[(size_t)(row0 + r) * 32 + c];
            As4[idx] = v;
        }
    }
    __syncthreads();

    const int rt = tid >> 4;   // 0..7  -> rows rt*8 .. rt*8+7
    const int ct = tid & 15;   // 0..15 -> cols ct*8 .. ct*8+7

    unsigned long long acc[8][4];
#pragma unroll
    for (int i = 0; i < 8; i++)
#pragma unroll
        for (int p = 0; p < 4; p++) acc[i][p] = 0ULL;

#pragma unroll 2
    for (int k4 = 0; k4 < D; k4 += 4) {
        float4 av[8];
#pragma unroll
        for (int i = 0; i < 8; i++)
            av[i] = *(const float4*)(As + (rt * 8 + i) * D + k4);
#pragma unroll
        for (int kk = 0; kk < 4; kk++) {
            const int k = k4 + kk;
            const ulonglong2* bp = (const ulonglong2*)(Bs + k * D + ct * 8);
            ulonglong2 q0 = bp[0];
            ulonglong2 q1 = bp[1];
#pragma unroll
            for (int i = 0; i < 8; i++) {
                float a = (kk == 0) ? av[i].x : (kk == 1) ? av[i].y
                          : (kk == 2) ? av[i].z : av[i].w;
                unsigned long long ad = dup2(a);
                acc[i][0] = fma2(ad, q0.x, acc[i][0]);
                acc[i][1] = fma2(ad, q0.y, acc[i][1]);
                acc[i][2] = fma2(ad, q1.x, acc[i][2]);
                acc[i][3] = fma2(ad, q1.y, acc[i][3]);
            }
        }
    }

    // epilogue: + bias, store
    float4 bias0 = *(const float4*)(bias + ct * 8);
    float4 bias1 = *(const float4*)(bias + ct * 8 + 4);
#pragma unroll
    for (int i = 0; i < 8; i++) {
        int r = row0 + rt * 8 + i;
        if (r < M) {
            float2 p0 = *(float2*)&acc[i][0];
            float2 p1 = *(float2*)&acc[i][1];
            float2 p2 = *(float2*)&acc[i][2];
            float2 p3 = *(float2*)&acc[i][3];
            float4 o0 = make_float4(p0.x + bias0.x, p0.y + bias0.y,
                                    p1.x + bias0.z, p1.y + bias0.w);
            float4 o1 = make_float4(p2.x + bias1.x, p2.y + bias1.y,
                                    p3.x + bias1.z, p3.y + bias1.w);
            *(float4*)(C + (size_t)r * D + ct * 8) = o0;
            *(float4*)(C + (size_t)r * D + ct * 8 + 4) = o1;
        }
    }
}

// ---------------- per-relation dst edge counts ----------------
__global__ void count_kernel(const int* __restrict__ dst, int E, float* cnt) {
    int g = blockIdx.x * blockDim.x + threadIdx.x;
    if (g < E) atomicAdd(cnt + dst[g], 1.0f);
}

// ---------------- edge scatter: out[dst] += H[src] * ew / cnt[dst] ----------------
// one warp per edge; each lane handles a float4 (vector red.global.add.v4.f32)
__global__ void edge_kernel(const int* __restrict__ src, const int* __restrict__ dst,
                            const float* __restrict__ ew, int E,
                            const float* __restrict__ H,
                            const float* __restrict__ cnt,
                            float* __restrict__ out) {
    int gid = blockIdx.x * blockDim.x + threadIdx.x;
    int e = gid >> 5;
    if (e >= E) return;
    int lane = gid & 31;
    int s = __ldg(src + e);
    int d = __ldg(dst + e);
    float c = __ldg(ew + e) / __ldg(cnt + d);
    float4 v = __ldg((const float4*)(H + (size_t)s * D) + lane);
    v.x *= c; v.y *= c; v.z *= c; v.w *= c;
    float* p = out + (size_t)d * D + lane * 4;
    asm volatile("red.global.add.v4.f32 [%0], {%1,%2,%3,%4};"
                 :: "l"(p), "f"(v.x), "f"(v.y), "f"(v.z), "f"(v.w)
                 : "memory");
}

// ---------------- relu ----------------
__global__ void relu_kernel(float4* out4, int n4) {
    int g = blockIdx.x * blockDim.x + threadIdx.x;
    if (g < n4) {
        float4 v = out4[g];
        v.x = fmaxf(v.x, 0.f); v.y = fmaxf(v.y, 0.f);
        v.z = fmaxf(v.z, 0.f); v.w = fmaxf(v.w, 0.f);
        out4[g] = v;
    }
}

extern "C" void kernel_launch(void* const* d_in, const int* in_sizes, int n_in,
                              void* d_out, int out_size) {
    const float* h_word  = (const float*)d_in[0];
    const float* h_topic = (const float*)d_in[1];
    // d_in[2] = h_doc (unused by the math)
    const float* W_ww = (const float*)d_in[3];
    const float* b_ww = (const float*)d_in[4];
    const float* W_wt = (const float*)d_in[5];
    const float* b_wt = (const float*)d_in[6];
    const float* W_wd = (const float*)d_in[7];
    const float* b_wd = (const float*)d_in[8];
    const float* W_td = (const float*)d_in[9];
    const float* b_td = (const float*)d_in[10];
    const float* W_tt = (const float*)d_in[11];
    const float* b_tt = (const float*)d_in[12];
    const int*   src_ww = (const int*)d_in[13];
    const int*   dst_ww = (const int*)d_in[14];
    const float* ew_ww  = (const float*)d_in[15];
    const int*   src_wt = (const int*)d_in[16];
    const int*   dst_wt = (const int*)d_in[17];
    const float* ew_wt  = (const float*)d_in[18];
    const int*   src_wd = (const int*)d_in[19];
    const int*   dst_wd = (const int*)d_in[20];
    const float* ew_wd  = (const float*)d_in[21];
    const int*   src_td = (const int*)d_in[22];
    const int*   dst_td = (const int*)d_in[23];
    const float* ew_td  = (const float*)d_in[24];
    const int*   src_tt = (const int*)d_in[25];
    const int*   dst_tt = (const int*)d_in[26];
    const float* ew_tt  = (const float*)d_in[27];

    const int E_ww = in_sizes[13];
    const int E_wt = in_sizes[16];
    const int E_wd = in_sizes[19];
    const int E_td = in_sizes[22];
    const int E_tt = in_sizes[25];

    float* out = (float*)d_out;

    // resolve scratch symbols
    float *hw, *ht, *cnt;
    cudaGetSymbolAddress((void**)&hw, g_hw);
    cudaGetSymbolAddress((void**)&ht, g_ht);
    cudaGetSymbolAddress((void**)&cnt, g_cnt);

    // count-array relation offsets
    float* cnt_ww = cnt;
    float* cnt_wt = cnt + NW;
    float* cnt_tt = cnt + NW + NT;
    float* cnt_wd = cnt + NW + 2 * NT;
    float* cnt_td = cnt + NW + 2 * NT + ND;
    // output row bases (word | topic | doc)
    float* out_word  = out;
    float* out_topic = out + (size_t)NW * D;
    float* out_doc   = out + (size_t)(NW + NT) * D;

    const int ncnt = NW + 2 * NT + 2 * ND;
    const int n4 = out_size / 4;

    // 1) zero output + counts
    {
        int nmax = (n4 > ncnt) ? n4 : ncnt;
        zero_kernel<<<(nmax + 255) / 256, 256>>>((float4*)out, n4, cnt, ncnt);
    }

    // 2) compose weights/biases
    compose_T1<<<D, D>>>(W_ww, W_wt);
    compose_B<<<D, D>>>(W_wd, W_td, W_tt);
    compose_bias<<<1, D>>>(b_ww, W_wt, b_wt, W_wd, b_wd, b_td, W_tt, b_tt);

    // 3) GEMMs (composed single linear per node type)
    {
        const int smem_bytes = (D * D + 64 * D) * (int)sizeof(float);  // 96KB
        cudaFuncSetAttribute(gemm128, cudaFuncAttributeMaxDynamicSharedMemorySize,
                             smem_bytes);
        float *Bw, *Bt, *bw, *bt;
        cudaGetSymbolAddress((void**)&Bw, g_Bw);
        cudaGetSymbolAddress((void**)&Bt, g_Bt);
        cudaGetSymbolAddress((void**)&bw, g_bw);
        cudaGetSymbolAddress((void**)&bt, g_bt);
        gemm128<<<(NW + 63) / 64, 128, smem_bytes>>>(h_word, NW, Bw, bw, hw);
        gemm128<<<(NT + 63) / 64, 128, smem_bytes>>>(h_topic, NT, Bt, bt, ht);
    }

    // 4) per-relation counts
    count_kernel<<<(E_ww + 255) / 256, 256>>>(dst_ww, E_ww, cnt_ww);
    count_kernel<<<(E_wt + 255) / 256, 256>>>(dst_wt, E_wt, cnt_wt);
    count_kernel<<<(E_tt + 255) / 256, 256>>>(dst_tt, E_tt, cnt_tt);
    count_kernel<<<(E_wd + 255) / 256, 256>>>(dst_wd, E_wd, cnt_wd);
    count_kernel<<<(E_td + 255) / 256, 256>>>(dst_td, E_td, cnt_td);

    // 5) edge scatter-reduce (mean via per-edge ew/cnt, cross-relation sum is free)
    auto eblocks = [](int E) { return (E * 32 + 255) / 256; };
    edge_kernel<<<eblocks(E_ww), 256>>>(src_ww, dst_ww, ew_ww, E_ww, hw, cnt_ww, out_word);
    edge_kernel<<<eblocks(E_wt), 256>>>(src_wt, dst_wt, ew_wt, E_wt, hw, cnt_wt, out_topic);
    edge_kernel<<<eblocks(E_tt), 256>>>(src_tt, dst_tt, ew_tt, E_tt, ht, cnt_tt, out_topic);
    edge_kernel<<<eblocks(E_wd), 256>>>(src_wd, dst_wd, ew_wd, E_wd, hw, cnt_wd, out_doc);
    edge_kernel<<<eblocks(E_td), 256>>>(src_td, dst_td, ew_td, E_td, ht, cnt_td, out_doc);

    // 6) relu
    relu_kernel<<<(n4 + 255) / 256, 256>>>((float4*)out, n4);
}

// round 2
// speedup vs baseline: 1.2326x; 1.2326x over previous
#include <cuda_runtime.h>
#include <cstdint>

#define D 128
#define NW 100000
#define NT 10000
#define ND 50000
#define NBLK_W 1563   // ceil(NW/64)
#define NBLK_T 157    // ceil(NT/64)

// ---------------- scratch (device globals: allocation-free) ----------------
__device__ float g_hw[(size_t)NW * D];        // composed-linear word features
__device__ float g_ht[(size_t)NT * D];        // composed-linear topic features
__device__ float g_cnt[NW + NT + NT + ND + ND];  // per-(relation,dst) 1/cnt
__device__ float g_T1[D * (D + 1)];           // T1 rows + tb1 as row 128
__device__ float g_Bw[D * D];
__device__ float g_Bt[D * D];
__device__ float g_bw[D];
__device__ float g_bt[D];

// ---------------- f32x2 helpers (Blackwell packed fp32 FMA) ----------------
__device__ __forceinline__ unsigned long long fma2(unsigned long long a,
                                                   unsigned long long b,
                                                   unsigned long long c) {
    unsigned long long d;
    asm("fma.rn.f32x2 %0, %1, %2, %3;" : "=l"(d) : "l"(a), "l"(b), "l"(c));
    return d;
}
__device__ __forceinline__ unsigned long long dup2(float x) {
    unsigned long long d;
    asm("mov.b64 %0, {%1, %1};" : "=l"(d) : "f"(x));
    return d;
}

// ---------------- zero outputs + counts ----------------
__global__ void zero_kernel(float4* out4, int n4, float* cnt, int ncnt) {
    int g = blockIdx.x * blockDim.x + threadIdx.x;
    if (g < n4) out4[g] = make_float4(0.f, 0.f, 0.f, 0.f);
    if (g < ncnt) cnt[g] = 0.f;
}

// ---------------- weight composition, pass 1 ----------------
// grid = 258 blocks, 128 threads. Shared-staged RHS matrix (padded, conflict-free).
//  b in [0,128):  T1 row b   = (col b of W_ww) . rows of W_wt
//  b == 128:      tb1        = b_ww . rows of W_wt + b_wt      (stored as T1 row 128)
//  b in [129,257): Bt row r  = (col r of W_td) . rows of W_tt  (r = b-129)
//  b == 257:      bt         = b_td . rows of W_tt + b_tt
__global__ void __launch_bounds__(128) compose1(
    const float* __restrict__ Www, const float* __restrict__ Wwt,
    const float* __restrict__ bww, const float* __restrict__ bwt,
    const float* __restrict__ Wtd, const float* __restrict__ Wtt,
    const float* __restrict__ btd, const float* __restrict__ btt) {
    extern __shared__ float sm[];
    float* Ws = sm;            // [128][129]
    float* Av = sm + 128 * 129;
    const int b = blockIdx.x;
    const int tid = threadIdx.x;
    const float* Wstage = (b < 129) ? Wwt : Wtt;
#pragma unroll 8
    for (int i = 0; i < 128; i++) Ws[i * 129 + tid] = Wstage[i * 128 + tid];
    if (b < 128)        Av[tid] = Www[tid * 128 + b];
    else if (b == 128)  Av[tid] = bww[tid];
    else if (b < 257)   Av[tid] = Wtd[tid * 128 + (b - 129)];
    else                Av[tid] = btd[tid];
    __syncthreads();
    float s = 0.f;
#pragma unroll 16
    for (int k = 0; k < 128; k++) s += Av[k] * Ws[tid * 129 + k];
    if (b < 128)        g_T1[b * 128 + tid] = s;
    else if (b == 128)  g_T1[128 * 128 + tid] = s + bwt[tid];
    else if (b < 257)   g_Bt[(b - 129) * 128 + tid] = s;
    else                g_bt[tid] = s + btt[tid];
}

// ---------------- weight composition, pass 2 ----------------
// grid = 129 blocks. b<128: Bw row b = T1 row b . rows of W_wd; b==128: bw = tb1 . W_wd + b_wd
__global__ void __launch_bounds__(128) compose2(
    const float* __restrict__ Wwd, const float* __restrict__ bwd) {
    extern __shared__ float sm[];
    float* Ws = sm;
    float* Av = sm + 128 * 129;
    const int b = blockIdx.x;
    const int tid = threadIdx.x;
#pragma unroll 8
    for (int i = 0; i < 128; i++) Ws[i * 129 + tid] = Wwd[i * 128 + tid];
    Av[tid] = g_T1[b * 128 + tid];
    __syncthreads();
    float s = 0.f;
#pragma unroll 16
    for (int k = 0; k < 128; k++) s += Av[k] * Ws[tid * 129 + k];
    if (b < 128) g_Bw[b * 128 + tid] = s;
    else         g_bw[tid] = s + bwd[tid];
}

// ---------------- GEMM: C[M,128] = A[M,128] @ B + bias (both node types, one launch) ----------------
__global__ void __launch_bounds__(128, 2)
gemm_dual(const float* __restrict__ Aw, const float* __restrict__ At,
          const float* __restrict__ Bww, const float* __restrict__ Btt,
          const float* __restrict__ bw, const float* __restrict__ bt,
          float* __restrict__ Cw, float* __restrict__ Ct) {
    extern __shared__ float smem[];
    float* Bs = smem;            // 128*128 floats
    float* As = smem + D * D;    // 64*128 floats
    const int tid = threadIdx.x;

    const float *A, *Bm, *bias;
    float* C;
    int M, row0;
    if (blockIdx.x < NBLK_W) {
        A = Aw; Bm = Bww; bias = bw; C = Cw; M = NW; row0 = blockIdx.x * 64;
    } else {
        A = At; Bm = Btt; bias = bt; C = Ct; M = NT; row0 = (blockIdx.x - NBLK_W) * 64;
    }

    {
        const float4* B4 = (const float4*)Bm;
        float4* Bs4 = (float4*)Bs;
#pragma unroll
        for (int i = 0; i < 32; i++) Bs4[tid + 128 * i] = B4[tid + 128 * i];
    }
    {
        const float4* A4 = (const float4*)A;
        float4* As4 = (float4*)As;
#pragma unroll
        for (int i = 0; i < 16; i++) {
            int idx = tid + 128 * i;
            int r = idx >> 5, c = idx & 31;
            float4 v = make_float4(0.f, 0.f, 0.f, 0.f);
            if (row0 + r < M) v = A4[(size_t)(row0 + r) * 32 + c];
            As4[idx] = v;
        }
    }
    __syncthreads();

    const int rt = tid >> 4;
    const int ct = tid & 15;

    unsigned long long acc[8][4];
#pragma unroll
    for (int i = 0; i < 8; i++)
#pragma unroll
        for (int p = 0; p < 4; p++) acc[i][p] = 0ULL;

#pragma unroll 2
    for (int k4 = 0; k4 < D; k4 += 4) {
        float4 av[8];
#pragma unroll
        for (int i = 0; i < 8; i++)
            av[i] = *(const float4*)(As + (rt * 8 + i) * D + k4);
#pragma unroll
        for (int kk = 0; kk < 4; kk++) {
            const int k = k4 + kk;
            const ulonglong2* bp = (const ulonglong2*)(Bs + k * D + ct * 8);
            ulonglong2 q0 = bp[0];
            ulonglong2 q1 = bp[1];
#pragma unroll
            for (int i = 0; i < 8; i++) {
                float a = (kk == 0) ? av[i].x : (kk == 1) ? av[i].y
                          : (kk == 2) ? av[i].z : av[i].w;
                unsigned long long ad = dup2(a);
                acc[i][0] = fma2(ad, q0.x, acc[i][0]);
                acc[i][1] = fma2(ad, q0.y, acc[i][1]);
                acc[i][2] = fma2(ad, q1.x, acc[i][2]);
                acc[i][3] = fma2(ad, q1.y, acc[i][3]);
            }
        }
    }

    float4 bias0 = *(const float4*)(bias + ct * 8);
    float4 bias1 = *(const float4*)(bias + ct * 8 + 4);
#pragma unroll
    for (int i = 0; i < 8; i++) {
        int r = row0 + rt * 8 + i;
        if (r < M) {
            float2 p0 = *(float2*)&acc[i][0];
            float2 p1 = *(float2*)&acc[i][1];
            float2 p2 = *(float2*)&acc[i][2];
            float2 p3 = *(float2*)&acc[i][3];
            float4 o0 = make_float4(p0.x + bias0.x, p0.y + bias0.y,
                                    p1.x + bias0.z, p1.y + bias0.w);
            float4 o1 = make_float4(p2.x + bias1.x, p2.y + bias1.y,
                                    p3.x + bias1.z, p3.y + bias1.w);
            *(float4*)(C + (size_t)r * D + ct * 8) = o0;
            *(float4*)(C + (size_t)r * D + ct * 8 + 4) = o1;
        }
    }
}

// ---------------- merged per-relation dst edge counts ----------------
struct CntArgs {
    const int* dst[5];
    float*     cnt[5];
    int        cum[6];   // cumulative edge boundaries
};
__global__ void count_all(CntArgs a) {
    int g = blockIdx.x * blockDim.x + threadIdx.x;
    if (g >= a.cum[5]) return;
    int r = 0;
    while (g >= a.cum[r + 1]) r++;
    int e = g - a.cum[r];
    atomicAdd(a.cnt[r] + __ldg(a.dst[r] + e), 1.0f);
}

// ---------------- reciprocal counts ----------------
__global__ void recip_kernel(float* cnt, int n) {
    int g = blockIdx.x * blockDim.x + threadIdx.x;
    if (g < n) cnt[g] = 1.0f / fmaxf(cnt[g], 1.0f);
}

// ---------------- merged edge scatter: out[dst] += H[src] * ew * rcnt[dst] ----------------
struct EdgeArgs {
    const int*   src[5];
    const int*   dst[5];
    const float* ew[5];
    const float* H[5];
    const float* rc[5];
    float*       out[5];
    int          cum[6];
};
__global__ void edge_all(EdgeArgs a) {
    int gid = blockIdx.x * blockDim.x + threadIdx.x;
    int e = gid >> 5;
    if (e >= a.cum[5]) return;
    int lane = gid & 31;
    int r = 0;
    while (e >= a.cum[r + 1]) r++;
    e -= a.cum[r];
    int s = __ldg(a.src[r] + e);
    int d = __ldg(a.dst[r] + e);
    float c = __ldg(a.ew[r] + e) * __ldg(a.rc[r] + d);
    float4 v = __ldg((const float4*)(a.H[r] + (size_t)s * D) + lane);
    v.x *= c; v.y *= c; v.z *= c; v.w *= c;
    float* p = a.out[r] + (size_t)d * D + lane * 4;
    asm volatile("red.global.add.v4.f32 [%0], {%1,%2,%3,%4};"
                 :: "l"(p), "f"(v.x), "f"(v.y), "f"(v.z), "f"(v.w)
                 : "memory");
}

// ---------------- relu ----------------
__global__ void relu_kernel(float4* out4, int n4) {
    int g = blockIdx.x * blockDim.x + threadIdx.x;
    if (g < n4) {
        float4 v = out4[g];
        v.x = fmaxf(v.x, 0.f); v.y = fmaxf(v.y, 0.f);
        v.z = fmaxf(v.z, 0.f); v.w = fmaxf(v.w, 0.f);
        out4[g] = v;
    }
}

extern "C" void kernel_launch(void* const* d_in, const int* in_sizes, int n_in,
                              void* d_out, int out_size) {
    const float* h_word  = (const float*)d_in[0];
    const float* h_topic = (const float*)d_in[1];
    const float* W_ww = (const float*)d_in[3];
    const float* b_ww = (const float*)d_in[4];
    const float* W_wt = (const float*)d_in[5];
    const float* b_wt = (const float*)d_in[6];
    const float* W_wd = (const float*)d_in[7];
    const float* b_wd = (const float*)d_in[8];
    const float* W_td = (const float*)d_in[9];
    const float* b_td = (const float*)d_in[10];
    const float* W_tt = (const float*)d_in[11];
    const float* b_tt = (const float*)d_in[12];
    const int*   src_ww = (const int*)d_in[13];
    const int*   dst_ww = (const int*)d_in[14];
    const float* ew_ww  = (const float*)d_in[15];
    const int*   src_wt = (const int*)d_in[16];
    const int*   dst_wt = (const int*)d_in[17];
    const float* ew_wt  = (const float*)d_in[18];
    const int*   src_wd = (const int*)d_in[19];
    const int*   dst_wd = (const int*)d_in[20];
    const float* ew_wd  = (const float*)d_in[21];
    const int*   src_td = (const int*)d_in[22];
    const int*   dst_td = (const int*)d_in[23];
    const float* ew_td  = (const float*)d_in[24];
    const int*   src_tt = (const int*)d_in[25];
    const int*   dst_tt = (const int*)d_in[26];
    const float* ew_tt  = (const float*)d_in[27];

    const int E_ww = in_sizes[13];
    const int E_wt = in_sizes[16];
    const int E_wd = in_sizes[19];
    const int E_td = in_sizes[22];
    const int E_tt = in_sizes[25];

    float* out = (float*)d_out;

    float *hw, *ht, *cnt, *Bw, *Bt, *bw, *bt;
    cudaGetSymbolAddress((void**)&hw, g_hw);
    cudaGetSymbolAddress((void**)&ht, g_ht);
    cudaGetSymbolAddress((void**)&cnt, g_cnt);
    cudaGetSymbolAddress((void**)&Bw, g_Bw);
    cudaGetSymbolAddress((void**)&Bt, g_Bt);
    cudaGetSymbolAddress((void**)&bw, g_bw);
    cudaGetSymbolAddress((void**)&bt, g_bt);

    float* cnt_ww = cnt;
    float* cnt_wt = cnt + NW;
    float* cnt_tt = cnt + NW + NT;
    float* cnt_wd = cnt + NW + 2 * NT;
    float* cnt_td = cnt + NW + 2 * NT + ND;
    float* out_word  = out;
    float* out_topic = out + (size_t)NW * D;
    float* out_doc   = out + (size_t)(NW + NT) * D;

    const int ncnt = NW + 2 * NT + 2 * ND;
    const int n4 = out_size / 4;

    // 1) zero output + counts
    {
        int nmax = (n4 > ncnt) ? n4 : ncnt;
        zero_kernel<<<(nmax + 255) / 256, 256>>>((float4*)out, n4, cnt, ncnt);
    }

    // 2) compose weights/biases (shared-staged, conflict-free)
    {
        const int csm = (128 * 129 + 128) * (int)sizeof(float);
        cudaFuncSetAttribute(compose1, cudaFuncAttributeMaxDynamicSharedMemorySize, csm);
        cudaFuncSetAttribute(compose2, cudaFuncAttributeMaxDynamicSharedMemorySize, csm);
        compose1<<<258, 128, csm>>>(W_ww, W_wt, b_ww, b_wt, W_td, W_tt, b_td, b_tt);
        compose2<<<129, 128, csm>>>(W_wd, b_wd);
    }

    // 3) merged counts + reciprocal
    {
        CntArgs ca;
        ca.dst[0] = dst_ww; ca.cnt[0] = cnt_ww;
        ca.dst[1] = dst_wt; ca.cnt[1] = cnt_wt;
        ca.dst[2] = dst_tt; ca.cnt[2] = cnt_tt;
        ca.dst[3] = dst_wd; ca.cnt[3] = cnt_wd;
        ca.dst[4] = dst_td; ca.cnt[4] = cnt_td;
        ca.cum[0] = 0;
        ca.cum[1] = E_ww;
        ca.cum[2] = E_ww + E_wt;
        ca.cum[3] = E_ww + E_wt + E_tt;
        ca.cum[4] = E_ww + E_wt + E_tt + E_wd;
        ca.cum[5] = E_ww + E_wt + E_tt + E_wd + E_td;
        count_all<<<(ca.cum[5] + 255) / 256, 256>>>(ca);
        recip_kernel<<<(ncnt + 255) / 256, 256>>>(cnt, ncnt);
    }

    // 4) GEMMs (single launch, composed linear per node type)
    {
        const int smem_bytes = (D * D + 64 * D) * (int)sizeof(float);
        cudaFuncSetAttribute(gemm_dual, cudaFuncAttributeMaxDynamicSharedMemorySize,
                             smem_bytes);
        gemm_dual<<<NBLK_W + NBLK_T, 128, smem_bytes>>>(h_word, h_topic, Bw, Bt,
                                                        bw, bt, hw, ht);
    }

    // 5) merged edge scatter-reduce
    {
        EdgeArgs ea;
        ea.src[0] = src_ww; ea.dst[0] = dst_ww; ea.ew[0] = ew_ww; ea.H[0] = hw; ea.rc[0] = cnt_ww; ea.out[0] = out_word;
        ea.src[1] = src_wt; ea.dst[1] = dst_wt; ea.ew[1] = ew_wt; ea.H[1] = hw; ea.rc[1] = cnt_wt; ea.out[1] = out_topic;
        ea.src[2] = src_tt; ea.dst[2] = dst_tt; ea.ew[2] = ew_tt; ea.H[2] = ht; ea.rc[2] = cnt_tt; ea.out[2] = out_topic;
        ea.src[3] = src_wd; ea.dst[3] = dst_wd; ea.ew[3] = ew_wd; ea.H[3] = hw; ea.rc[3] = cnt_wd; ea.out[3] = out_doc;
        ea.src[4] = src_td; ea.dst[4] = dst_td; ea.ew[4] = ew_td; ea.H[4] = ht; ea.rc[4] = cnt_td; ea.out[4] = out_doc;
        ea.cum[0] = 0;
        ea.cum[1] = E_ww;
        ea.cum[2] = E_ww + E_wt;
        ea.cum[3] = E_ww + E_wt + E_tt;
        ea.cum[4] = E_ww + E_wt + E_tt + E_wd;
        ea.cum[5] = E_ww + E_wt + E_tt + E_wd + E_td;
        long long tot = (long long)ea.cum[5] * 32;
        edge_all<<<(int)((tot + 255) / 256), 256>>>(ea);
    }

    // 6) relu
    relu_kernel<<<(n4 + 255) / 256, 256>>>((float4*)out, n4);
}

// round 3
// speedup vs baseline: 1.5521x; 1.2592x over previous
#include <cuda_runtime.h>
#include <cstdint>

#define D 128
#define NW 100000
#define NT 10000
#define ND 50000
#define NV (NW + NT + NT + ND + ND)   // 220000 virtual (relation,dst) nodes
#define NROW (NW + NT + ND)           // 160000 output rows
#define NBLK_W 1563   // ceil(NW/64)
#define NBLK_T 157    // ceil(NT/64)
#define SCAN_BLK 54   // ceil(NV/4096)

// ---------------- scratch (device globals: allocation-free) ----------------
__device__ float g_h[(size_t)(NW + NT) * D];  // unified composed features (word|topic)
__device__ int   g_cnt[NV];
__device__ int   g_offs[NV];
__device__ int   g_cursor[NV];
__device__ float g_rcnt[NV];
__device__ int   g_bsum[SCAN_BLK];
__device__ int2  g_perm[600000];              // (global_src, ew*rcnt) per edge, CSR order
__device__ float g_T1[D * (D + 1)];
__device__ float g_Bw[D * D];
__device__ float g_Bt[D * D];
__device__ float g_bw[D];
__device__ float g_bt[D];

// ---------------- f32x2 helpers ----------------
__device__ __forceinline__ unsigned long long fma2(unsigned long long a,
                                                   unsigned long long b,
                                                   unsigned long long c) {
    unsigned long long d;
    asm("fma.rn.f32x2 %0, %1, %2, %3;" : "=l"(d) : "l"(a), "l"(b), "l"(c));
    return d;
}
__device__ __forceinline__ unsigned long long dup2(float x) {
    unsigned long long d;
    asm("mov.b64 %0, {%1, %1};" : "=l"(d) : "f"(x));
    return d;
}

// ---------------- zero counts ----------------
__global__ void zero_cnt(int* cnt, int n) {
    int g = blockIdx.x * blockDim.x + threadIdx.x;
    if (g < n) cnt[g] = 0;
}

// ---------------- weight composition (as R2; ~4us) ----------------
__global__ void __launch_bounds__(128) compose1(
    const float* __restrict__ Www, const float* __restrict__ Wwt,
    const float* __restrict__ bww, const float* __restrict__ bwt,
    const float* __restrict__ Wtd, const float* __restrict__ Wtt,
    const float* __restrict__ btd, const float* __restrict__ btt) {
    extern __shared__ float sm[];
    float* Ws = sm;
    float* Av = sm + 128 * 129;
    const int b = blockIdx.x;
    const int tid = threadIdx.x;
    const float* Wstage = (b < 129) ? Wwt : Wtt;
#pragma unroll 8
    for (int i = 0; i < 128; i++) Ws[i * 129 + tid] = Wstage[i * 128 + tid];
    if (b < 128)        Av[tid] = Www[tid * 128 + b];
    else if (b == 128)  Av[tid] = bww[tid];
    else if (b < 257)   Av[tid] = Wtd[tid * 128 + (b - 129)];
    else                Av[tid] = btd[tid];
    __syncthreads();
    float s = 0.f;
#pragma unroll 16
    for (int k = 0; k < 128; k++) s += Av[k] * Ws[tid * 129 + k];
    if (b < 128)        g_T1[b * 128 + tid] = s;
    else if (b == 128)  g_T1[128 * 128 + tid] = s + bwt[tid];
    else if (b < 257)   g_Bt[(b - 129) * 128 + tid] = s;
    else                g_bt[tid] = s + btt[tid];
}
__global__ void __launch_bounds__(128) compose2(
    const float* __restrict__ Wwd, const float* __restrict__ bwd) {
    extern __shared__ float sm[];
    float* Ws = sm;
    float* Av = sm + 128 * 129;
    const int b = blockIdx.x;
    const int tid = threadIdx.x;
#pragma unroll 8
    for (int i = 0; i < 128; i++) Ws[i * 129 + tid] = Wwd[i * 128 + tid];
    Av[tid] = g_T1[b * 128 + tid];
    __syncthreads();
    float s = 0.f;
#pragma unroll 16
    for (int k = 0; k < 128; k++) s += Av[k] * Ws[tid * 129 + k];
    if (b < 128) g_Bw[b * 128 + tid] = s;
    else         g_bw[tid] = s + bwd[tid];
}

// ---------------- GEMM: C[M,128] = A[M,128] @ B + bias (both node types) ----------------
__global__ void __launch_bounds__(128, 2)
gemm_dual(const float* __restrict__ Aw, const float* __restrict__ At,
          float* __restrict__ H) {
    extern __shared__ float smem[];
    float* Bs = smem;
    float* As = smem + D * D;
    const int tid = threadIdx.x;

    const float *A, *Bm, *bias;
    float* C;
    int M, row0;
    if (blockIdx.x < NBLK_W) {
        A = Aw; Bm = g_Bw; bias = g_bw; C = H; M = NW; row0 = blockIdx.x * 64;
    } else {
        A = At; Bm = g_Bt; bias = g_bt; C = H + (size_t)NW * D; M = NT;
        row0 = (blockIdx.x - NBLK_W) * 64;
    }

    {
        const float4* B4 = (const float4*)Bm;
        float4* Bs4 = (float4*)Bs;
#pragma unroll
        for (int i = 0; i < 32; i++) Bs4[tid + 128 * i] = B4[tid + 128 * i];
    }
    {
        const float4* A4 = (const float4*)A;
        float4* As4 = (float4*)As;
#pragma unroll
        for (int i = 0; i < 16; i++) {
            int idx = tid + 128 * i;
            int r = idx >> 5, c = idx & 31;
            float4 v = make_float4(0.f, 0.f, 0.f, 0.f);
            if (row0 + r < M) v = A4[(size_t)(row0 + r) * 32 + c];
            As4[idx] = v;
        }
    }
    __syncthreads();

    const int rt = tid >> 4;
    const int ct = tid & 15;

    unsigned long long acc[8][4];
#pragma unroll
    for (int i = 0; i < 8; i++)
#pragma unroll
        for (int p = 0; p < 4; p++) acc[i][p] = 0ULL;

#pragma unroll 2
    for (int k4 = 0; k4 < D; k4 += 4) {
        float4 av[8];
#pragma unroll
        for (int i = 0; i < 8; i++)
            av[i] = *(const float4*)(As + (rt * 8 + i) * D + k4);
#pragma unroll
        for (int kk = 0; kk < 4; kk++) {
            const int k = k4 + kk;
            const ulonglong2* bp = (const ulonglong2*)(Bs + k * D + ct * 8);
            ulonglong2 q0 = bp[0];
            ulonglong2 q1 = bp[1];
#pragma unroll
            for (int i = 0; i < 8; i++) {
                float a = (kk == 0) ? av[i].x : (kk == 1) ? av[i].y
                          : (kk == 2) ? av[i].z : av[i].w;
                unsigned long long ad = dup2(a);
                acc[i][0] = fma2(ad, q0.x, acc[i][0]);
                acc[i][1] = fma2(ad, q0.y, acc[i][1]);
                acc[i][2] = fma2(ad, q1.x, acc[i][2]);
                acc[i][3] = fma2(ad, q1.y, acc[i][3]);
            }
        }
    }

    float4 bias0 = *(const float4*)(bias + ct * 8);
    float4 bias1 = *(const float4*)(bias + ct * 8 + 4);
#pragma unroll
    for (int i = 0; i < 8; i++) {
        int r = row0 + rt * 8 + i;
        if (r < M) {
            float2 p0 = *(float2*)&acc[i][0];
            float2 p1 = *(float2*)&acc[i][1];
            float2 p2 = *(float2*)&acc[i][2];
            float2 p3 = *(float2*)&acc[i][3];
            float4 o0 = make_float4(p0.x + bias0.x, p0.y + bias0.y,
                                    p1.x + bias0.z, p1.y + bias0.w);
            float4 o1 = make_float4(p2.x + bias1.x, p2.y + bias1.y,
                                    p3.x + bias1.z, p3.y + bias1.w);
            *(float4*)(C + (size_t)r * D + ct * 8) = o0;
            *(float4*)(C + (size_t)r * D + ct * 8 + 4) = o1;
        }
    }
}

// ---------------- counts (int4 vectorized, fire-and-forget) ----------------
struct Cnt4Args {
    const int4* dst4[5];
    int vbase[5];
    int cum4[6];
};
__global__ void count_all(Cnt4Args a, int* __restrict__ cnt) {
    int g = blockIdx.x * blockDim.x + threadIdx.x;
    if (g >= a.cum4[5]) return;
    int r = 0;
    while (g >= a.cum4[r + 1]) r++;
    int4 d = __ldg(a.dst4[r] + (g - a.cum4[r]));
    int* base = cnt + a.vbase[r];
    atomicAdd(base + d.x, 1);
    atomicAdd(base + d.y, 1);
    atomicAdd(base + d.z, 1);
    atomicAdd(base + d.w, 1);
}

// ---------------- scan pass A: per-block exclusive scan (4096 elems/block) ----
__global__ void __launch_bounds__(1024) scanA(const int* __restrict__ cnt, int n,
                                              int* __restrict__ offs,
                                              float* __restrict__ rcnt,
                                              int* __restrict__ bsum) {
    __shared__ int wsum[32];
    const int tid = threadIdx.x;
    const int base = blockIdx.x * 4096 + tid * 4;
    int v[4];
#pragma unroll
    for (int k = 0; k < 4; k++) v[k] = (base + k < n) ? cnt[base + k] : 0;
#pragma unroll
    for (int k = 0; k < 4; k++)
        if (base + k < n) rcnt[base + k] = 1.0f / (float)max(v[k], 1);
    int t = v[0] + v[1] + v[2] + v[3];
    const int lane = tid & 31, w = tid >> 5;
    int inc = t;
#pragma unroll
    for (int dlt = 1; dlt < 32; dlt <<= 1) {
        int x = __shfl_up_sync(0xffffffffu, inc, dlt);
        if (lane >= dlt) inc += x;
    }
    if (lane == 31) wsum[w] = inc;
    __syncthreads();
    if (w == 0) {
        int si = wsum[lane];
#pragma unroll
        for (int dlt = 1; dlt < 32; dlt <<= 1) {
            int x = __shfl_up_sync(0xffffffffu, si, dlt);
            if (lane >= dlt) si += x;
        }
        wsum[lane] = si;
    }
    __syncthreads();
    int o = inc - t + (w > 0 ? wsum[w - 1] : 0);
#pragma unroll
    for (int k = 0; k < 4; k++) {
        if (base + k < n) offs[base + k] = o;
        o += v[k];
    }
    if (tid == 0) bsum[blockIdx.x] = wsum[31];
}

// ---------------- scan pass B: exclusive scan of block sums (tiny) ----------
__global__ void scanB(int* bsum, int nb) {
    __shared__ int s[64];
    int tid = threadIdx.x;
    if (tid < nb) s[tid] = bsum[tid];
    __syncthreads();
    if (tid == 0) {
        int acc = 0;
        for (int i = 0; i < nb; i++) { int t = s[i]; s[i] = acc; acc += t; }
    }
    __syncthreads();
    if (tid < nb) bsum[tid] = s[tid];
}

// ---------------- scan pass C: add block offsets, init cursors --------------
__global__ void __launch_bounds__(1024) scanC(int* __restrict__ offs, int n,
                                              const int* __restrict__ bsum,
                                              int* __restrict__ cursor) {
    int base = blockIdx.x * 4096 + threadIdx.x * 4;
    int add = bsum[blockIdx.x];
#pragma unroll
    for (int k = 0; k < 4; k++) {
        int i = base + k;
        if (i < n) {
            int o = offs[i] + add;
            offs[i] = o;
            cursor[i] = o;
        }
    }
}

// ---------------- CSR fill: perm[pos] = (global_src, ew * rcnt) --------------
struct FillArgs {
    const int*   src[5];
    const int*   dst[5];
    const float* ew[5];
    int vbase[5];
    int soff[5];
    int cum[6];
};
__global__ void fill_kernel(FillArgs a, const float* __restrict__ rcnt,
                            int* __restrict__ cursor, int2* __restrict__ perm) {
    int g = blockIdx.x * blockDim.x + threadIdx.x;
    if (g >= a.cum[5]) return;
    int r = 0;
    while (g >= a.cum[r + 1]) r++;
    int e = g - a.cum[r];
    int v = a.vbase[r] + __ldg(a.dst[r] + e);
    float c = __ldg(a.ew[r] + e) * __ldg(rcnt + v);
    int pos = atomicAdd(cursor + v, 1);
    perm[pos] = make_int2(__ldg(a.src[r] + e) + a.soff[r], __float_as_int(c));
}

// ---------------- gather: one warp per output row, fused relu ---------------
__global__ void __launch_bounds__(256) gather_kernel(
    const int2* __restrict__ perm, const int* __restrict__ offs,
    const int* __restrict__ cnt, const float* __restrict__ H,
    float* __restrict__ out) {
    int gid = blockIdx.x * 256 + threadIdx.x;
    int row = gid >> 5;
    if (row >= NROW) return;
    int lane = gid & 31;

    int v0, v1;
    if (row < NW) { v0 = row; v1 = -1; }
    else if (row < NW + NT) { int t = row - NW; v0 = NW + t; v1 = NW + NT + t; }
    else { int d = row - NW - NT; v0 = NW + 2 * NT + d; v1 = NW + 2 * NT + ND + d; }

    float4 acc = make_float4(0.f, 0.f, 0.f, 0.f);
#pragma unroll
    for (int pass = 0; pass < 2; pass++) {
        int v = pass ? v1 : v0;
        if (v < 0) continue;
        int s = __ldg(offs + v);
        int e = s + __ldg(cnt + v);
        for (int i = s; i < e; i += 32) {
            int m = min(32, e - i);
            int2 md = (lane < m) ? __ldg(perm + i + lane) : make_int2(0, 0);
            int j = 0;
            for (; j + 1 < m; j += 2) {
                int s0 = __shfl_sync(0xffffffffu, md.x, j);
                float c0 = __int_as_float(__shfl_sync(0xffffffffu, md.y, j));
                int s1 = __shfl_sync(0xffffffffu, md.x, j + 1);
                float c1 = __int_as_float(__shfl_sync(0xffffffffu, md.y, j + 1));
                float4 h0 = __ldg((const float4*)(H + (size_t)s0 * D) + lane);
                float4 h1 = __ldg((const float4*)(H + (size_t)s1 * D) + lane);
                acc.x = fmaf(c0, h0.x, fmaf(c1, h1.x, acc.x));
                acc.y = fmaf(c0, h0.y, fmaf(c1, h1.y, acc.y));
                acc.z = fmaf(c0, h0.z, fmaf(c1, h1.z, acc.z));
                acc.w = fmaf(c0, h0.w, fmaf(c1, h1.w, acc.w));
            }
            if (j < m) {
                int s0 = __shfl_sync(0xffffffffu, md.x, j);
                float c0 = __int_as_float(__shfl_sync(0xffffffffu, md.y, j));
                float4 h0 = __ldg((const float4*)(H + (size_t)s0 * D) + lane);
                acc.x = fmaf(c0, h0.x, acc.x);
                acc.y = fmaf(c0, h0.y, acc.y);
                acc.z = fmaf(c0, h0.z, acc.z);
                acc.w = fmaf(c0, h0.w, acc.w);
            }
        }
    }
    float4 o = make_float4(fmaxf(acc.x, 0.f), fmaxf(acc.y, 0.f),
                           fmaxf(acc.z, 0.f), fmaxf(acc.w, 0.f));
    *(float4*)(out + (size_t)row * D + lane * 4) = o;
}

extern "C" void kernel_launch(void* const* d_in, const int* in_sizes, int n_in,
                              void* d_out, int out_size) {
    const float* h_word  = (const float*)d_in[0];
    const float* h_topic = (const float*)d_in[1];
    const float* W_ww = (const float*)d_in[3];
    const float* b_ww = (const float*)d_in[4];
    const float* W_wt = (const float*)d_in[5];
    const float* b_wt = (const float*)d_in[6];
    const float* W_wd = (const float*)d_in[7];
    const float* b_wd = (const float*)d_in[8];
    const float* W_td = (const float*)d_in[9];
    const float* b_td = (const float*)d_in[10];
    const float* W_tt = (const float*)d_in[11];
    const float* b_tt = (const float*)d_in[12];
    const int*   src_ww = (const int*)d_in[13];
    const int*   dst_ww = (const int*)d_in[14];
    const float* ew_ww  = (const float*)d_in[15];
    const int*   src_wt = (const int*)d_in[16];
    const int*   dst_wt = (const int*)d_in[17];
    const float* ew_wt  = (const float*)d_in[18];
    const int*   src_wd = (const int*)d_in[19];
    const int*   dst_wd = (const int*)d_in[20];
    const float* ew_wd  = (const float*)d_in[21];
    const int*   src_td = (const int*)d_in[22];
    const int*   dst_td = (const int*)d_in[23];
    const float* ew_td  = (const float*)d_in[24];
    const int*   src_tt = (const int*)d_in[25];
    const int*   dst_tt = (const int*)d_in[26];
    const float* ew_tt  = (const float*)d_in[27];

    const int E_ww = in_sizes[13];
    const int E_wt = in_sizes[16];
    const int E_wd = in_sizes[19];
    const int E_td = in_sizes[22];
    const int E_tt = in_sizes[25];

    float* out = (float*)d_out;

    float *H, *rcnt;
    int *cnt, *offs, *cursor, *bsum;
    int2* perm;
    cudaGetSymbolAddress((void**)&H, g_h);
    cudaGetSymbolAddress((void**)&cnt, g_cnt);
    cudaGetSymbolAddress((void**)&offs, g_offs);
    cudaGetSymbolAddress((void**)&cursor, g_cursor);
    cudaGetSymbolAddress((void**)&rcnt, g_rcnt);
    cudaGetSymbolAddress((void**)&bsum, g_bsum);
    cudaGetSymbolAddress((void**)&perm, g_perm);

    // virtual-node bases per relation (order: ww, wt, tt, wd, td)
    const int vb_ww = 0;
    const int vb_wt = NW;
    const int vb_tt = NW + NT;
    const int vb_wd = NW + 2 * NT;
    const int vb_td = NW + 2 * NT + ND;

    // 1) zero counts
    zero_cnt<<<(NV + 1023) / 1024, 1024>>>(cnt, NV);

    // 2) compose weights/biases
    {
        const int csm = (128 * 129 + 128) * (int)sizeof(float);
        cudaFuncSetAttribute(compose1, cudaFuncAttributeMaxDynamicSharedMemorySize, csm);
        cudaFuncSetAttribute(compose2, cudaFuncAttributeMaxDynamicSharedMemorySize, csm);
        compose1<<<258, 128, csm>>>(W_ww, W_wt, b_ww, b_wt, W_td, W_tt, b_td, b_tt);
        compose2<<<129, 128, csm>>>(W_wd, b_wd);
    }

    // 3) counts (int4)
    {
        Cnt4Args ca;
        ca.dst4[0] = (const int4*)dst_ww; ca.vbase[0] = vb_ww;
        ca.dst4[1] = (const int4*)dst_wt; ca.vbase[1] = vb_wt;
        ca.dst4[2] = (const int4*)dst_tt; ca.vbase[2] = vb_tt;
        ca.dst4[3] = (const int4*)dst_wd; ca.vbase[3] = vb_wd;
        ca.dst4[4] = (const int4*)dst_td; ca.vbase[4] = vb_td;
        ca.cum4[0] = 0;
        ca.cum4[1] = E_ww / 4;
        ca.cum4[2] = ca.cum4[1] + E_wt / 4;
        ca.cum4[3] = ca.cum4[2] + E_tt / 4;
        ca.cum4[4] = ca.cum4[3] + E_wd / 4;
        ca.cum4[5] = ca.cum4[4] + E_td / 4;
        count_all<<<(ca.cum4[5] + 255) / 256, 256>>>(ca, cnt);
    }

    // 4) scan -> offsets + cursors + reciprocal counts
    scanA<<<SCAN_BLK, 1024>>>(cnt, NV, offs, rcnt, bsum);
    scanB<<<1, 64>>>(bsum, SCAN_BLK);
    scanC<<<SCAN_BLK, 1024>>>(offs, NV, bsum, cursor);

    // 5) CSR fill
    {
        FillArgs fa;
        fa.src[0] = src_ww; fa.dst[0] = dst_ww; fa.ew[0] = ew_ww; fa.vbase[0] = vb_ww; fa.soff[0] = 0;
        fa.src[1] = src_wt; fa.dst[1] = dst_wt; fa.ew[1] = ew_wt; fa.vbase[1] = vb_wt; fa.soff[1] = 0;
        fa.src[2] = src_tt; fa.dst[2] = dst_tt; fa.ew[2] = ew_tt; fa.vbase[2] = vb_tt; fa.soff[2] = NW;
        fa.src[3] = src_wd; fa.dst[3] = dst_wd; fa.ew[3] = ew_wd; fa.vbase[3] = vb_wd; fa.soff[3] = 0;
        fa.src[4] = src_td; fa.dst[4] = dst_td; fa.ew[4] = ew_td; fa.vbase[4] = vb_td; fa.soff[4] = NW;
        fa.cum[0] = 0;
        fa.cum[1] = E_ww;
        fa.cum[2] = fa.cum[1] + E_wt;
        fa.cum[3] = fa.cum[2] + E_tt;
        fa.cum[4] = fa.cum[3] + E_wd;
        fa.cum[5] = fa.cum[4] + E_td;
        fill_kernel<<<(fa.cum[5] + 255) / 256, 256>>>(fa, rcnt, cursor, perm);
    }

    // 6) GEMM (word + topic in one launch, writes unified H)
    {
        const int smem_bytes = (D * D + 64 * D) * (int)sizeof(float);
        cudaFuncSetAttribute(gemm_dual, cudaFuncAttributeMaxDynamicSharedMemorySize,
                             smem_bytes);
        gemm_dual<<<NBLK_W + NBLK_T, 128, smem_bytes>>>(h_word, h_topic, H);
    }

    // 7) gather with fused relu (no zero pass, no relu pass, no atomics)
    gather_kernel<<<(NROW * 32 + 255) / 256, 256>>>(perm, offs, cnt, H, out);
}

// round 5
// speedup vs baseline: 1.9048x; 1.2272x over previous
#include <cuda_runtime.h>
#include <cuda_bf16.h>
#include <cstdint>

#define D 128
#define NW 100000
#define NT 10000
#define ND 50000
#define NV (NW + NT + NT + ND + ND)   // 220000 virtual (relation,dst) nodes
#define NROW (NW + NT + ND)           // 160000 output rows
#define SCAN_BLK 54                   // ceil(NV/4096)
#define TILES_W 782                   // ceil(NW/128)
#define TILES_T 79                    // ceil(NT/128)

// ---------------- scratch (device globals: allocation-free) ----------------
__device__ float g_h[(size_t)(NW + NT) * D];  // unified composed features (word|topic)
__device__ int   g_cnt[NV];
__device__ int   g_offs[NV];
__device__ int   g_cursor[NV];
__device__ float g_rcnt[NV];
__device__ int   g_bsum[SCAN_BLK];
__device__ int2  g_perm[600000];
__device__ float g_T1[D * (D + 1)];
__device__ float g_bw[D];
__device__ float g_bt[D];
// composed B, bf16 split, plain [n][k] row-major (n = output dim, k = input dim)
__device__ __nv_bfloat16 g_Bwh[D * D];
__device__ __nv_bfloat16 g_Bwl[D * D];
__device__ __nv_bfloat16 g_Bth[D * D];
__device__ __nv_bfloat16 g_Btl[D * D];

// ---------------- mma/ldmatrix helpers (plain PTX, sm_80+) ----------------
__device__ __forceinline__ uint32_t smem_u32(const void* p) {
    uint32_t a;
    asm("{ .reg .u64 t; cvta.to.shared.u64 t, %1; cvt.u32.u64 %0, t; }" : "=r"(a) : "l"(p));
    return a;
}
__device__ __forceinline__ void ldmx4(uint32_t* r, uint32_t addr) {
    asm volatile("ldmatrix.sync.aligned.m8n8.x4.shared.b16 {%0,%1,%2,%3}, [%4];"
                 : "=r"(r[0]), "=r"(r[1]), "=r"(r[2]), "=r"(r[3]) : "r"(addr));
}
#define MMA_BF16(c0, c1, c2, c3, a0, a1, a2, a3, b0, b1)                        \
    asm volatile(                                                               \
        "mma.sync.aligned.m16n8k16.row.col.f32.bf16.bf16.f32 "                  \
        "{%0,%1,%2,%3}, {%4,%5,%6,%7}, {%8,%9}, {%0,%1,%2,%3};"                 \
        : "+f"(c0), "+f"(c1), "+f"(c2), "+f"(c3)                                \
        : "r"(a0), "r"(a1), "r"(a2), "r"(a3), "r"(b0), "r"(b1))

// ---------------- zero counts ----------------
__global__ void zero_cnt(int* cnt, int n) {
    int g = blockIdx.x * blockDim.x + threadIdx.x;
    if (g < n) cnt[g] = 0;
}

// ---------------- weight composition ----------------
//  b in [0,128):  T1 row b   = (col b of W_ww) . rows of W_wt
//  b == 128:      tb1        = b_ww . W_wt + b_wt  (T1 row 128)
//  b in [129,257): Bt col k=b-129 for all n -> bf16 split, [n][k]
//  b == 257:      bt         = b_td . W_tt + b_tt
__global__ void __launch_bounds__(128) compose1(
    const float* __restrict__ Www, const float* __restrict__ Wwt,
    const float* __restrict__ bww, const float* __restrict__ bwt,
    const float* __restrict__ Wtd, const float* __restrict__ Wtt,
    const float* __restrict__ btd, const float* __restrict__ btt) {
    extern __shared__ float sm[];
    float* Ws = sm;
    float* Av = sm + 128 * 129;
    const int b = blockIdx.x;
    const int tid = threadIdx.x;
    const float* Wstage = (b < 129) ? Wwt : Wtt;
#pragma unroll 8
    for (int i = 0; i < 128; i++) Ws[i * 129 + tid] = Wstage[i * 128 + tid];
    if (b < 128)        Av[tid] = Www[tid * 128 + b];
    else if (b == 128)  Av[tid] = bww[tid];
    else if (b < 257)   Av[tid] = Wtd[tid * 128 + (b - 129)];
    else                Av[tid] = btd[tid];
    __syncthreads();
    float s = 0.f;
#pragma unroll 16
    for (int k = 0; k < 128; k++) s += Av[k] * Ws[tid * 129 + k];
    if (b < 128)        g_T1[b * 128 + tid] = s;
    else if (b == 128)  g_T1[128 * 128 + tid] = s + bwt[tid];
    else if (b < 257) {
        int k = b - 129;                  // n = tid, k = input dim
        __nv_bfloat16 hh = __float2bfloat16(s);
        g_Bth[tid * 128 + k] = hh;
        g_Btl[tid * 128 + k] = __float2bfloat16(s - __bfloat162float(hh));
    } else              g_bt[tid] = s + btt[tid];
}
//  b<128: Bw col k=b for all n=tid -> bf16 split [n][k];  b==128: bw = tb1 . W_wd + b_wd
__global__ void __launch_bounds__(128) compose2(
    const float* __restrict__ Wwd, const float* __restrict__ bwd) {
    extern __shared__ float sm[];
    float* Ws = sm;
    float* Av = sm + 128 * 129;
    const int b = blockIdx.x;
    const int tid = threadIdx.x;
#pragma unroll 8
    for (int i = 0; i < 128; i++) Ws[i * 129 + tid] = Wwd[i * 128 + tid];
    Av[tid] = g_T1[b * 128 + tid];
    __syncthreads();
    float s = 0.f;
#pragma unroll 16
    for (int k = 0; k < 128; k++) s += Av[k] * Ws[tid * 129 + k];
    if (b < 128) {
        __nv_bfloat16 hh = __float2bfloat16(s);
        g_Bwh[tid * 128 + b] = hh;
        g_Bwl[tid * 128 + b] = __float2bfloat16(s - __bfloat162float(hh));
    } else g_bw[tid] = s + bwd[tid];
}

// ---------------- tensor-core GEMM: H[M,128] = A @ Bcomp^T + bias --------------
// bf16 split-2 via mma.sync m16n8k16: D = Ah*Bh + Al*Bh + Ah*Bl (fp32 accum).
// 256 threads, 128 rows/block, warp w owns rows [w*16, w*16+16).
// smem: padded stride 136 elems (272B) -> conflict-free ldmatrix.
__global__ void __launch_bounds__(256, 1)
gemm_mma(const float* __restrict__ Aw, const float* __restrict__ At,
         float* __restrict__ H) {
    extern __shared__ __align__(16) char smem[];
    __nv_bfloat16* As_hi = (__nv_bfloat16*)smem;                 // [128][136]
    __nv_bfloat16* As_lo = (__nv_bfloat16*)(smem + 34816);
    __nv_bfloat16* Bs_hi = (__nv_bfloat16*)(smem + 69632);
    __nv_bfloat16* Bs_lo = (__nv_bfloat16*)(smem + 104448);
    const int tid = threadIdx.x;
    const int wid = tid >> 5, lane = tid & 31;

    const float* A;
    const __nv_bfloat16 *Bh, *Bl;
    const float* bias;
    float* C;
    int M, row0;
    if (blockIdx.x < TILES_W) {
        A = Aw; Bh = g_Bwh; Bl = g_Bwl; bias = g_bw; C = H;
        M = NW; row0 = blockIdx.x * 128;
    } else {
        A = At; Bh = g_Bth; Bl = g_Btl; bias = g_bt; C = H + (size_t)NW * D;
        M = NT; row0 = (blockIdx.x - TILES_W) * 128;
    }

    // stage B hi/lo (16384 bf16 each) into padded smem
    {
        const uint32_t* bh = (const uint32_t*)Bh;
        const uint32_t* bl = (const uint32_t*)Bl;
        uint32_t* dh = (uint32_t*)Bs_hi;
        uint32_t* dl = (uint32_t*)Bs_lo;
#pragma unroll
        for (int i = 0; i < 32; i++) {
            int idx = tid + 256 * i;          // word index 0..8191
            int n = idx >> 6, w = idx & 63;
            dh[n * 68 + w] = __ldg(bh + idx);
            dl[n * 68 + w] = __ldg(bl + idx);
        }
    }
    // stage A: fp32 -> bf16 hi/lo split
    {
#pragma unroll
        for (int i = 0; i < 16; i++) {
            int idx = tid + 256 * i;          // float4 index 0..4095
            int r = idx >> 5, c4 = idx & 31;
            float4 f = (row0 + r < M)
                ? __ldg((const float4*)(A + (size_t)(row0 + r) * D) + c4)
                : make_float4(0.f, 0.f, 0.f, 0.f);
            __nv_bfloat16 h0 = __float2bfloat16(f.x), h1 = __float2bfloat16(f.y);
            __nv_bfloat16 h2 = __float2bfloat16(f.z), h3 = __float2bfloat16(f.w);
            __nv_bfloat162 ph0, ph1, pl0, pl1;
            ph0.x = h0; ph0.y = h1; ph1.x = h2; ph1.y = h3;
            pl0.x = __float2bfloat16(f.x - __bfloat162float(h0));
            pl0.y = __float2bfloat16(f.y - __bfloat162float(h1));
            pl1.x = __float2bfloat16(f.z - __bfloat162float(h2));
            pl1.y = __float2bfloat16(f.w - __bfloat162float(h3));
            int base = r * 136 + c4 * 4;
            *(__nv_bfloat162*)(As_hi + base)     = ph0;
            *(__nv_bfloat162*)(As_hi + base + 2) = ph1;
            *(__nv_bfloat162*)(As_lo + base)     = pl0;
            *(__nv_bfloat162*)(As_lo + base + 2) = pl1;
        }
    }
    __syncthreads();

    const uint32_t as_hi_b = smem_u32(As_hi), as_lo_b = smem_u32(As_lo);
    const uint32_t bs_hi_b = smem_u32(Bs_hi), bs_lo_b = smem_u32(Bs_lo);
    const int lr = lane & 7, lm = lane >> 3;

    // load all A fragments for this warp's 16 rows: 8 ksteps, hi+lo
    uint32_t ah[8][4], al[8][4];
    {
        uint32_t arow = (uint32_t)(wid * 16 + lr + (lm & 1) * 8);
        uint32_t acol = (uint32_t)((lm >> 1) * 8);
        uint32_t abase = (arow * 136 + acol) * 2;
#pragma unroll
        for (int ks = 0; ks < 8; ks++) {
            ldmx4(ah[ks], as_hi_b + abase + ks * 32);
            ldmx4(al[ks], as_lo_b + abase + ks * 32);
        }
    }

    const int g = lane >> 2, t = lane & 3;
    const int orow0 = row0 + wid * 16 + g;
    // B lane address: mats 0,1 from hi; 2,3 from lo; col +8 for odd mats
    const uint32_t bbase_sel = (lm >= 2) ? bs_lo_b : bs_hi_b;
    const uint32_t bcol = (uint32_t)((lm & 1) * 8);

#pragma unroll 4
    for (int nt = 0; nt < 16; nt++) {
        float c0 = 0.f, c1 = 0.f, c2 = 0.f, c3 = 0.f;
        uint32_t baddr = bbase_sel + (((uint32_t)(nt * 8 + lr)) * 136 + bcol) * 2;
#pragma unroll
        for (int ks = 0; ks < 8; ks++) {
            uint32_t b[4];
            ldmx4(b, baddr + ks * 32);   // b[0],b[1]=Bh frag; b[2],b[3]=Bl frag
            MMA_BF16(c0, c1, c2, c3, ah[ks][0], ah[ks][1], ah[ks][2], ah[ks][3], b[0], b[1]);
            MMA_BF16(c0, c1, c2, c3, al[ks][0], al[ks][1], al[ks][2], al[ks][3], b[0], b[1]);
            MMA_BF16(c0, c1, c2, c3, ah[ks][0], ah[ks][1], ah[ks][2], ah[ks][3], b[2], b[3]);
        }
        int col = nt * 8 + t * 2;
        float2 b2 = __ldg((const float2*)(bias + col));
        if (orow0 < M)
            *(float2*)(C + (size_t)orow0 * D + col) = make_float2(c0 + b2.x, c1 + b2.y);
        if (orow0 + 8 < M)
            *(float2*)(C + (size_t)(orow0 + 8) * D + col) = make_float2(c2 + b2.x, c3 + b2.y);
    }
}

// ---------------- counts (int4 vectorized, fire-and-forget) ----------------
struct Cnt4Args {
    const int4* dst4[5];
    int vbase[5];
    int cum4[6];
};
__global__ void count_all(Cnt4Args a, int* __restrict__ cnt) {
    int g = blockIdx.x * blockDim.x + threadIdx.x;
    if (g >= a.cum4[5]) return;
    int r = 0;
    while (g >= a.cum4[r + 1]) r++;
    int4 d = __ldg(a.dst4[r] + (g - a.cum4[r]));
    int* base = cnt + a.vbase[r];
    atomicAdd(base + d.x, 1);
    atomicAdd(base + d.y, 1);
    atomicAdd(base + d.z, 1);
    atomicAdd(base + d.w, 1);
}

// ---------------- scan pass A ----------------
__global__ void __launch_bounds__(1024) scanA(const int* __restrict__ cnt, int n,
                                              int* __restrict__ offs,
                                              float* __restrict__ rcnt,
                                              int* __restrict__ bsum) {
    __shared__ int wsum[32];
    const int tid = threadIdx.x;
    const int base = blockIdx.x * 4096 + tid * 4;
    int v[4];
#pragma unroll
    for (int k = 0; k < 4; k++) v[k] = (base + k < n) ? cnt[base + k] : 0;
#pragma unroll
    for (int k = 0; k < 4; k++)
        if (base + k < n) rcnt[base + k] = 1.0f / (float)max(v[k], 1);
    int t = v[0] + v[1] + v[2] + v[3];
    const int lane = tid & 31, w = tid >> 5;
    int inc = t;
#pragma unroll
    for (int dlt = 1; dlt < 32; dlt <<= 1) {
        int x = __shfl_up_sync(0xffffffffu, inc, dlt);
        if (lane >= dlt) inc += x;
    }
    if (lane == 31) wsum[w] = inc;
    __syncthreads();
    if (w == 0) {
        int si = wsum[lane];
#pragma unroll
        for (int dlt = 1; dlt < 32; dlt <<= 1) {
            int x = __shfl_up_sync(0xffffffffu, si, dlt);
            if (lane >= dlt) si += x;
        }
        wsum[lane] = si;
    }
    __syncthreads();
    int o = inc - t + (w > 0 ? wsum[w - 1] : 0);
#pragma unroll
    for (int k = 0; k < 4; k++) {
        if (base + k < n) offs[base + k] = o;
        o += v[k];
    }
    if (tid == 0) bsum[blockIdx.x] = wsum[31];
}

// ---------------- scan pass B ----------------
__global__ void scanB(int* bsum, int nb) {
    __shared__ int s[64];
    int tid = threadIdx.x;
    if (tid < nb) s[tid] = bsum[tid];
    __syncthreads();
    if (tid == 0) {
        int acc = 0;
        for (int i = 0; i < nb; i++) { int t = s[i]; s[i] = acc; acc += t; }
    }
    __syncthreads();
    if (tid < nb) bsum[tid] = s[tid];
}

// ---------------- scan pass C ----------------
__global__ void __launch_bounds__(1024) scanC(int* __restrict__ offs, int n,
                                              const int* __restrict__ bsum,
                                              int* __restrict__ cursor) {
    int base = blockIdx.x * 4096 + threadIdx.x * 4;
    int add = bsum[blockIdx.x];
#pragma unroll
    for (int k = 0; k < 4; k++) {
        int i = base + k;
        if (i < n) {
            int o = offs[i] + add;
            offs[i] = o;
            cursor[i] = o;
        }
    }
}

// ---------------- CSR fill ----------------
struct FillArgs {
    const int*   src[5];
    const int*   dst[5];
    const float* ew[5];
    int vbase[5];
    int soff[5];
    int cum[6];
};
__global__ void fill_kernel(FillArgs a, const float* __restrict__ rcnt,
                            int* __restrict__ cursor, int2* __restrict__ perm) {
    int g = blockIdx.x * blockDim.x + threadIdx.x;
    if (g >= a.cum[5]) return;
    int r = 0;
    while (g >= a.cum[r + 1]) r++;
    int e = g - a.cum[r];
    int v = a.vbase[r] + __ldg(a.dst[r] + e);
    float c = __ldg(a.ew[r] + e) * __ldg(rcnt + v);
    int pos = atomicAdd(cursor + v, 1);
    perm[pos] = make_int2(__ldg(a.src[r] + e) + a.soff[r], __float_as_int(c));
}

// ---------------- gather: one warp per output row, fused relu ---------------
__global__ void __launch_bounds__(256) gather_kernel(
    const int2* __restrict__ perm, const int* __restrict__ offs,
    const int* __restrict__ cnt, const float* __restrict__ H,
    float* __restrict__ out) {
    int gid = blockIdx.x * 256 + threadIdx.x;
    int row = gid >> 5;
    if (row >= NROW) return;
    int lane = gid & 31;

    int v0, v1;
    if (row < NW) { v0 = row; v1 = -1; }
    else if (row < NW + NT) { int t = row - NW; v0 = NW + t; v1 = NW + NT + t; }
    else { int d = row - NW - NT; v0 = NW + 2 * NT + d; v1 = NW + 2 * NT + ND + d; }

    float4 acc = make_float4(0.f, 0.f, 0.f, 0.f);
#pragma unroll
    for (int pass = 0; pass < 2; pass++) {
        int v = pass ? v1 : v0;
        if (v < 0) continue;
        int s = __ldg(offs + v);
        int e = s + __ldg(cnt + v);
        for (int i = s; i < e; i += 32) {
            int m = min(32, e - i);
            int2 md = (lane < m) ? __ldg(perm + i + lane) : make_int2(0, 0);
            int j = 0;
            for (; j + 1 < m; j += 2) {
                int s0 = __shfl_sync(0xffffffffu, md.x, j);
                float c0 = __int_as_float(__shfl_sync(0xffffffffu, md.y, j));
                int s1 = __shfl_sync(0xffffffffu, md.x, j + 1);
                float c1 = __int_as_float(__shfl_sync(0xffffffffu, md.y, j + 1));
                float4 h0 = __ldg((const float4*)(H + (size_t)s0 * D) + lane);
                float4 h1 = __ldg((const float4*)(H + (size_t)s1 * D) + lane);
                acc.x = fmaf(c0, h0.x, fmaf(c1, h1.x, acc.x));
                acc.y = fmaf(c0, h0.y, fmaf(c1, h1.y, acc.y));
                acc.z = fmaf(c0, h0.z, fmaf(c1, h1.z, acc.z));
                acc.w = fmaf(c0, h0.w, fmaf(c1, h1.w, acc.w));
            }
            if (j < m) {
                int s0 = __shfl_sync(0xffffffffu, md.x, j);
                float c0 = __int_as_float(__shfl_sync(0xffffffffu, md.y, j));
                float4 h0 = __ldg((const float4*)(H + (size_t)s0 * D) + lane);
                acc.x = fmaf(c0, h0.x, acc.x);
                acc.y = fmaf(c0, h0.y, acc.y);
                acc.z = fmaf(c0, h0.z, acc.z);
                acc.w = fmaf(c0, h0.w, acc.w);
            }
        }
    }
    float4 o = make_float4(fmaxf(acc.x, 0.f), fmaxf(acc.y, 0.f),
                           fmaxf(acc.z, 0.f), fmaxf(acc.w, 0.f));
    *(float4*)(out + (size_t)row * D + lane * 4) = o;
}

extern "C" void kernel_launch(void* const* d_in, const int* in_sizes, int n_in,
                              void* d_out, int out_size) {
    const float* h_word  = (const float*)d_in[0];
    const float* h_topic = (const float*)d_in[1];
    const float* W_ww = (const float*)d_in[3];
    const float* b_ww = (const float*)d_in[4];
    const float* W_wt = (const float*)d_in[5];
    const float* b_wt = (const float*)d_in[6];
    const float* W_wd = (const float*)d_in[7];
    const float* b_wd = (const float*)d_in[8];
    const float* W_td = (const float*)d_in[9];
    const float* b_td = (const float*)d_in[10];
    const float* W_tt = (const float*)d_in[11];
    const float* b_tt = (const float*)d_in[12];
    const int*   src_ww = (const int*)d_in[13];
    const int*   dst_ww = (const int*)d_in[14];
    const float* ew_ww  = (const float*)d_in[15];
    const int*   src_wt = (const int*)d_in[16];
    const int*   dst_wt = (const int*)d_in[17];
    const float* ew_wt  = (const float*)d_in[18];
    const int*   src_wd = (const int*)d_in[19];
    const int*   dst_wd = (const int*)d_in[20];
    const float* ew_wd  = (const float*)d_in[21];
    const int*   src_td = (const int*)d_in[22];
    const int*   dst_td = (const int*)d_in[23];
    const float* ew_td  = (const float*)d_in[24];
    const int*   src_tt = (const int*)d_in[25];
    const int*   dst_tt = (const int*)d_in[26];
    const float* ew_tt  = (const float*)d_in[27];

    const int E_ww = in_sizes[13];
    const int E_wt = in_sizes[16];
    const int E_wd = in_sizes[19];
    const int E_td = in_sizes[22];
    const int E_tt = in_sizes[25];

    float* out = (float*)d_out;

    float *H, *rcnt;
    int *cnt, *offs, *cursor, *bsum;
    int2* perm;
    cudaGetSymbolAddress((void**)&H, g_h);
    cudaGetSymbolAddress((void**)&cnt, g_cnt);
    cudaGetSymbolAddress((void**)&offs, g_offs);
    cudaGetSymbolAddress((void**)&cursor, g_cursor);
    cudaGetSymbolAddress((void**)&rcnt, g_rcnt);
    cudaGetSymbolAddress((void**)&bsum, g_bsum);
    cudaGetSymbolAddress((void**)&perm, g_perm);

    const int vb_ww = 0;
    const int vb_wt = NW;
    const int vb_tt = NW + NT;
    const int vb_wd = NW + 2 * NT;
    const int vb_td = NW + 2 * NT + ND;

    // 1) zero counts
    zero_cnt<<<(NV + 1023) / 1024, 1024>>>(cnt, NV);

    // 2) compose weights/biases (emits bf16 split B, plain [n][k])
    {
        const int csm = (128 * 129 + 128) * (int)sizeof(float);
        cudaFuncSetAttribute(compose1, cudaFuncAttributeMaxDynamicSharedMemorySize, csm);
        cudaFuncSetAttribute(compose2, cudaFuncAttributeMaxDynamicSharedMemorySize, csm);
        compose1<<<258, 128, csm>>>(W_ww, W_wt, b_ww, b_wt, W_td, W_tt, b_td, b_tt);
        compose2<<<129, 128, csm>>>(W_wd, b_wd);
    }

    // 3) counts (int4)
    {
        Cnt4Args ca;
        ca.dst4[0] = (const int4*)dst_ww; ca.vbase[0] = vb_ww;
        ca.dst4[1] = (const int4*)dst_wt; ca.vbase[1] = vb_wt;
        ca.dst4[2] = (const int4*)dst_tt; ca.vbase[2] = vb_tt;
        ca.dst4[3] = (const int4*)dst_wd; ca.vbase[3] = vb_wd;
        ca.dst4[4] = (const int4*)dst_td; ca.vbase[4] = vb_td;
        ca.cum4[0] = 0;
        ca.cum4[1] = E_ww / 4;
        ca.cum4[2] = ca.cum4[1] + E_wt / 4;
        ca.cum4[3] = ca.cum4[2] + E_tt / 4;
        ca.cum4[4] = ca.cum4[3] + E_wd / 4;
        ca.cum4[5] = ca.cum4[4] + E_td / 4;
        count_all<<<(ca.cum4[5] + 255) / 256, 256>>>(ca, cnt);
    }

    // 4) scan -> offsets + cursors + reciprocal counts
    scanA<<<SCAN_BLK, 1024>>>(cnt, NV, offs, rcnt, bsum);
    scanB<<<1, 64>>>(bsum, SCAN_BLK);
    scanC<<<SCAN_BLK, 1024>>>(offs, NV, bsum, cursor);

    // 5) CSR fill
    {
        FillArgs fa;
        fa.src[0] = src_ww; fa.dst[0] = dst_ww; fa.ew[0] = ew_ww; fa.vbase[0] = vb_ww; fa.soff[0] = 0;
        fa.src[1] = src_wt; fa.dst[1] = dst_wt; fa.ew[1] = ew_wt; fa.vbase[1] = vb_wt; fa.soff[1] = 0;
        fa.src[2] = src_tt; fa.dst[2] = dst_tt; fa.ew[2] = ew_tt; fa.vbase[2] = vb_tt; fa.soff[2] = NW;
        fa.src[3] = src_wd; fa.dst[3] = dst_wd; fa.ew[3] = ew_wd; fa.vbase[3] = vb_wd; fa.soff[3] = 0;
        fa.src[4] = src_td; fa.dst[4] = dst_td; fa.ew[4] = ew_td; fa.vbase[4] = vb_td; fa.soff[4] = NW;
        fa.cum[0] = 0;
        fa.cum[1] = E_ww;
        fa.cum[2] = fa.cum[1] + E_wt;
        fa.cum[3] = fa.cum[2] + E_tt;
        fa.cum[4] = fa.cum[3] + E_wd;
        fa.cum[5] = fa.cum[4] + E_td;
        fill_kernel<<<(fa.cum[5] + 255) / 256, 256>>>(fa, rcnt, cursor, perm);
    }

    // 6) tensor-core GEMM (word + topic, one launch)
    {
        const int smem_bytes = 139264;  // As hi/lo + Bs hi/lo, padded stride 136
        cudaFuncSetAttribute(gemm_mma, cudaFuncAttributeMaxDynamicSharedMemorySize,
                             smem_bytes);
        gemm_mma<<<TILES_W + TILES_T, 256, smem_bytes>>>(h_word, h_topic, H);
    }

    // 7) gather with fused relu
    gather_kernel<<<(NROW * 32 + 255) / 256, 256>>>(perm, offs, cnt, H, out);
}

// round 6
// speedup vs baseline: 2.0545x; 1.0786x over previous
#include <cuda_runtime.h>
#include <cuda_bf16.h>
#include <cstdint>

#define D 128
#define NW 100000
#define NT 10000
#define ND 50000
#define NV (NW + NT + NT + ND + ND)   // 220000 virtual (relation,dst) nodes
#define NROW (NW + NT + ND)           // 160000 output rows
#define SCAN_BLK 54                   // ceil(NV/4096)
#define TILES_W 782                   // ceil(NW/128)
#define TILES_T 79                    // ceil(NT/128)

// ---------------- scratch (device globals: allocation-free) ----------------
__device__ float g_h[(size_t)(NW + NT) * D];  // unified composed features (word|topic)
__device__ int   g_cnt[NV];
__device__ int   g_offs[NV];
__device__ int   g_cursor[NV];
__device__ float g_rcnt[NV];
__device__ int   g_bsum[SCAN_BLK];
__device__ int2  g_perm[600000];
__device__ float g_T1[D * (D + 1)];
__device__ float g_bw[D];
__device__ float g_bt[D];
// composed B, bf16 split, plain [n][k] row-major (n = output dim, k = input dim)
__device__ __nv_bfloat16 g_Bwh[D * D];
__device__ __nv_bfloat16 g_Bwl[D * D];
__device__ __nv_bfloat16 g_Bth[D * D];
__device__ __nv_bfloat16 g_Btl[D * D];

// ---------------- mma/ldmatrix helpers (plain PTX, sm_80+) ----------------
__device__ __forceinline__ uint32_t smem_u32(const void* p) {
    uint32_t a;
    asm("{ .reg .u64 t; cvta.to.shared.u64 t, %1; cvt.u32.u64 %0, t; }" : "=r"(a) : "l"(p));
    return a;
}
__device__ __forceinline__ void ldmx4(uint32_t* r, uint32_t addr) {
    asm volatile("ldmatrix.sync.aligned.m8n8.x4.shared.b16 {%0,%1,%2,%3}, [%4];"
                 : "=r"(r[0]), "=r"(r[1]), "=r"(r[2]), "=r"(r[3]) : "r"(addr));
}
#define MMA_BF16(c0, c1, c2, c3, a0, a1, a2, a3, b0, b1)                        \
    asm volatile(                                                               \
        "mma.sync.aligned.m16n8k16.row.col.f32.bf16.bf16.f32 "                  \
        "{%0,%1,%2,%3}, {%4,%5,%6,%7}, {%8,%9}, {%0,%1,%2,%3};"                 \
        : "+f"(c0), "+f"(c1), "+f"(c2), "+f"(c3)                                \
        : "r"(a0), "r"(a1), "r"(a2), "r"(a3), "r"(b0), "r"(b1))

// ---------------- weight composition ----------------
__global__ void __launch_bounds__(128) compose1(
    const float* __restrict__ Www, const float* __restrict__ Wwt,
    const float* __restrict__ bww, const float* __restrict__ bwt,
    const float* __restrict__ Wtd, const float* __restrict__ Wtt,
    const float* __restrict__ btd, const float* __restrict__ btt) {
    extern __shared__ float sm[];
    float* Ws = sm;
    float* Av = sm + 128 * 129;
    const int b = blockIdx.x;
    const int tid = threadIdx.x;
    const float* Wstage = (b < 129) ? Wwt : Wtt;
#pragma unroll 8
    for (int i = 0; i < 128; i++) Ws[i * 129 + tid] = Wstage[i * 128 + tid];
    if (b < 128)        Av[tid] = Www[tid * 128 + b];
    else if (b == 128)  Av[tid] = bww[tid];
    else if (b < 257)   Av[tid] = Wtd[tid * 128 + (b - 129)];
    else                Av[tid] = btd[tid];
    __syncthreads();
    float s = 0.f;
#pragma unroll 16
    for (int k = 0; k < 128; k++) s += Av[k] * Ws[tid * 129 + k];
    if (b < 128)        g_T1[b * 128 + tid] = s;
    else if (b == 128)  g_T1[128 * 128 + tid] = s + bwt[tid];
    else if (b < 257) {
        int k = b - 129;                  // n = tid, k = input dim
        __nv_bfloat16 hh = __float2bfloat16(s);
        g_Bth[tid * 128 + k] = hh;
        g_Btl[tid * 128 + k] = __float2bfloat16(s - __bfloat162float(hh));
    } else              g_bt[tid] = s + btt[tid];
}
__global__ void __launch_bounds__(128) compose2(
    const float* __restrict__ Wwd, const float* __restrict__ bwd) {
    extern __shared__ float sm[];
    float* Ws = sm;
    float* Av = sm + 128 * 129;
    const int b = blockIdx.x;
    const int tid = threadIdx.x;
#pragma unroll 8
    for (int i = 0; i < 128; i++) Ws[i * 129 + tid] = Wwd[i * 128 + tid];
    Av[tid] = g_T1[b * 128 + tid];
    __syncthreads();
    float s = 0.f;
#pragma unroll 16
    for (int k = 0; k < 128; k++) s += Av[k] * Ws[tid * 129 + k];
    if (b < 128) {
        __nv_bfloat16 hh = __float2bfloat16(s);
        g_Bwh[tid * 128 + b] = hh;
        g_Bwl[tid * 128 + b] = __float2bfloat16(s - __bfloat162float(hh));
    } else g_bw[tid] = s + bwd[tid];
}

// ---------------- tensor-core GEMM: H[M,128] = A @ Bcomp^T + bias --------------
__global__ void __launch_bounds__(256, 1)
gemm_mma(const float* __restrict__ Aw, const float* __restrict__ At,
         float* __restrict__ H) {
    extern __shared__ __align__(16) char smem[];
    __nv_bfloat16* As_hi = (__nv_bfloat16*)smem;                 // [128][136]
    __nv_bfloat16* As_lo = (__nv_bfloat16*)(smem + 34816);
    __nv_bfloat16* Bs_hi = (__nv_bfloat16*)(smem + 69632);
    __nv_bfloat16* Bs_lo = (__nv_bfloat16*)(smem + 104448);
    const int tid = threadIdx.x;
    const int wid = tid >> 5, lane = tid & 31;

    const float* A;
    const __nv_bfloat16 *Bh, *Bl;
    const float* bias;
    float* C;
    int M, row0;
    if (blockIdx.x < TILES_W) {
        A = Aw; Bh = g_Bwh; Bl = g_Bwl; bias = g_bw; C = H;
        M = NW; row0 = blockIdx.x * 128;
    } else {
        A = At; Bh = g_Bth; Bl = g_Btl; bias = g_bt; C = H + (size_t)NW * D;
        M = NT; row0 = (blockIdx.x - TILES_W) * 128;
    }

    {
        const uint32_t* bh = (const uint32_t*)Bh;
        const uint32_t* bl = (const uint32_t*)Bl;
        uint32_t* dh = (uint32_t*)Bs_hi;
        uint32_t* dl = (uint32_t*)Bs_lo;
#pragma unroll
        for (int i = 0; i < 32; i++) {
            int idx = tid + 256 * i;
            int n = idx >> 6, w = idx & 63;
            dh[n * 68 + w] = __ldg(bh + idx);
            dl[n * 68 + w] = __ldg(bl + idx);
        }
    }
    {
#pragma unroll
        for (int i = 0; i < 16; i++) {
            int idx = tid + 256 * i;
            int r = idx >> 5, c4 = idx & 31;
            float4 f = (row0 + r < M)
                ? __ldg((const float4*)(A + (size_t)(row0 + r) * D) + c4)
                : make_float4(0.f, 0.f, 0.f, 0.f);
            __nv_bfloat16 h0 = __float2bfloat16(f.x), h1 = __float2bfloat16(f.y);
            __nv_bfloat16 h2 = __float2bfloat16(f.z), h3 = __float2bfloat16(f.w);
            __nv_bfloat162 ph0, ph1, pl0, pl1;
            ph0.x = h0; ph0.y = h1; ph1.x = h2; ph1.y = h3;
            pl0.x = __float2bfloat16(f.x - __bfloat162float(h0));
            pl0.y = __float2bfloat16(f.y - __bfloat162float(h1));
            pl1.x = __float2bfloat16(f.z - __bfloat162float(h2));
            pl1.y = __float2bfloat16(f.w - __bfloat162float(h3));
            int base = r * 136 + c4 * 4;
            *(__nv_bfloat162*)(As_hi + base)     = ph0;
            *(__nv_bfloat162*)(As_hi + base + 2) = ph1;
            *(__nv_bfloat162*)(As_lo + base)     = pl0;
            *(__nv_bfloat162*)(As_lo + base + 2) = pl1;
        }
    }
    __syncthreads();

    const uint32_t as_hi_b = smem_u32(As_hi), as_lo_b = smem_u32(As_lo);
    const uint32_t bs_hi_b = smem_u32(Bs_hi), bs_lo_b = smem_u32(Bs_lo);
    const int lr = lane & 7, lm = lane >> 3;

    uint32_t ah[8][4], al[8][4];
    {
        uint32_t arow = (uint32_t)(wid * 16 + lr + (lm & 1) * 8);
        uint32_t acol = (uint32_t)((lm >> 1) * 8);
        uint32_t abase = (arow * 136 + acol) * 2;
#pragma unroll
        for (int ks = 0; ks < 8; ks++) {
            ldmx4(ah[ks], as_hi_b + abase + ks * 32);
            ldmx4(al[ks], as_lo_b + abase + ks * 32);
        }
    }

    const int g = lane >> 2, t = lane & 3;
    const int orow0 = row0 + wid * 16 + g;
    const uint32_t bbase_sel = (lm >= 2) ? bs_lo_b : bs_hi_b;
    const uint32_t bcol = (uint32_t)((lm & 1) * 8);

#pragma unroll 4
    for (int nt = 0; nt < 16; nt++) {
        float c0 = 0.f, c1 = 0.f, c2 = 0.f, c3 = 0.f;
        uint32_t baddr = bbase_sel + (((uint32_t)(nt * 8 + lr)) * 136 + bcol) * 2;
#pragma unroll
        for (int ks = 0; ks < 8; ks++) {
            uint32_t b[4];
            ldmx4(b, baddr + ks * 32);
            MMA_BF16(c0, c1, c2, c3, ah[ks][0], ah[ks][1], ah[ks][2], ah[ks][3], b[0], b[1]);
            MMA_BF16(c0, c1, c2, c3, al[ks][0], al[ks][1], al[ks][2], al[ks][3], b[0], b[1]);
            MMA_BF16(c0, c1, c2, c3, ah[ks][0], ah[ks][1], ah[ks][2], ah[ks][3], b[2], b[3]);
        }
        int col = nt * 8 + t * 2;
        float2 b2 = __ldg((const float2*)(bias + col));
        if (orow0 < M)
            *(float2*)(C + (size_t)orow0 * D + col) = make_float2(c0 + b2.x, c1 + b2.y);
        if (orow0 + 8 < M)
            *(float2*)(C + (size_t)(orow0 + 8) * D + col) = make_float2(c2 + b2.x, c3 + b2.y);
    }
}

// ---------------- counts (int4 vectorized, fire-and-forget) ----------------
struct Cnt4Args {
    const int4* dst4[5];
    int vbase[5];
    int cum4[6];
};
__global__ void count_all(Cnt4Args a, int* __restrict__ cnt) {
    int g = blockIdx.x * blockDim.x + threadIdx.x;
    if (g >= a.cum4[5]) return;
    int r = 0;
    while (g >= a.cum4[r + 1]) r++;
    int4 d = __ldg(a.dst4[r] + (g - a.cum4[r]));
    int* base = cnt + a.vbase[r];
    atomicAdd(base + d.x, 1);
    atomicAdd(base + d.y, 1);
    atomicAdd(base + d.z, 1);
    atomicAdd(base + d.w, 1);
}

// ---------------- scan pass A: per-block exclusive scan + rcnt --------------
__global__ void __launch_bounds__(1024) scanA(const int* __restrict__ cnt, int n,
                                              int* __restrict__ offs,
                                              float* __restrict__ rcnt,
                                              int* __restrict__ bsum) {
    __shared__ int wsum[32];
    const int tid = threadIdx.x;
    const int base = blockIdx.x * 4096 + tid * 4;
    int v[4];
#pragma unroll
    for (int k = 0; k < 4; k++) v[k] = (base + k < n) ? cnt[base + k] : 0;
#pragma unroll
    for (int k = 0; k < 4; k++)
        if (base + k < n) rcnt[base + k] = 1.0f / (float)max(v[k], 1);
    int t = v[0] + v[1] + v[2] + v[3];
    const int lane = tid & 31, w = tid >> 5;
    int inc = t;
#pragma unroll
    for (int dlt = 1; dlt < 32; dlt <<= 1) {
        int x = __shfl_up_sync(0xffffffffu, inc, dlt);
        if (lane >= dlt) inc += x;
    }
    if (lane == 31) wsum[w] = inc;
    __syncthreads();
    if (w == 0) {
        int si = wsum[lane];
#pragma unroll
        for (int dlt = 1; dlt < 32; dlt <<= 1) {
            int x = __shfl_up_sync(0xffffffffu, si, dlt);
            if (lane >= dlt) si += x;
        }
        wsum[lane] = si;
    }
    __syncthreads();
    int o = inc - t + (w > 0 ? wsum[w - 1] : 0);
#pragma unroll
    for (int k = 0; k < 4; k++) {
        if (base + k < n) offs[base + k] = o;
        o += v[k];
    }
    if (tid == 0) bsum[blockIdx.x] = wsum[31];
}

// ---------------- scan pass C (merged B): add block-prefix, init cursors ----
__global__ void __launch_bounds__(1024) scanC(int* __restrict__ offs, int n,
                                              const int* __restrict__ bsum,
                                              int* __restrict__ cursor) {
    __shared__ int pref;
    const int tid = threadIdx.x;
    // threads 0..31 compute prefix-sum of bsum[0..blockIdx.x) via warp reduce
    if (tid < 32) {
        int acc = 0;
        for (int i = tid; i < blockIdx.x; i += 32) acc += bsum[i];
#pragma unroll
        for (int dlt = 16; dlt > 0; dlt >>= 1)
            acc += __shfl_down_sync(0xffffffffu, acc, dlt);
        if (tid == 0) pref = acc;
    }
    __syncthreads();
    const int add = pref;
    int base = blockIdx.x * 4096 + tid * 4;
#pragma unroll
    for (int k = 0; k < 4; k++) {
        int i = base + k;
        if (i < n) {
            int o = offs[i] + add;
            offs[i] = o;
            cursor[i] = o;
        }
    }
}

// ---------------- CSR fill ----------------
struct FillArgs {
    const int*   src[5];
    const int*   dst[5];
    const float* ew[5];
    int vbase[5];
    int soff[5];
    int cum[6];
};
__global__ void fill_kernel(FillArgs a, const float* __restrict__ rcnt,
                            int* __restrict__ cursor, int2* __restrict__ perm) {
    int g = blockIdx.x * blockDim.x + threadIdx.x;
    if (g >= a.cum[5]) return;
    int r = 0;
    while (g >= a.cum[r + 1]) r++;
    int e = g - a.cum[r];
    int v = a.vbase[r] + __ldg(a.dst[r] + e);
    float c = __ldg(a.ew[r] + e) * __ldg(rcnt + v);
    int pos = atomicAdd(cursor + v, 1);
    perm[pos] = make_int2(__ldg(a.src[r] + e) + a.soff[r], __float_as_int(c));
}

// ---------------- gather: one warp per output row, fused relu ---------------
__global__ void __launch_bounds__(256) gather_kernel(
    const int2* __restrict__ perm, const int* __restrict__ offs,
    const int* __restrict__ cnt, const float* __restrict__ H,
    float* __restrict__ out) {
    int gid = blockIdx.x * 256 + threadIdx.x;
    int row = gid >> 5;
    if (row >= NROW) return;
    int lane = gid & 31;

    int v0, v1;
    if (row < NW) { v0 = row; v1 = -1; }
    else if (row < NW + NT) { int t = row - NW; v0 = NW + t; v1 = NW + NT + t; }
    else { int d = row - NW - NT; v0 = NW + 2 * NT + d; v1 = NW + 2 * NT + ND + d; }

    float4 acc = make_float4(0.f, 0.f, 0.f, 0.f);
#pragma unroll
    for (int pass = 0; pass < 2; pass++) {
        int v = pass ? v1 : v0;
        if (v < 0) continue;
        int s = __ldg(offs + v);
        int e = s + __ldg(cnt + v);
        for (int i = s; i < e; i += 32) {
            int m = min(32, e - i);
            int2 md = (lane < m) ? __ldg(perm + i + lane) : make_int2(0, 0);
            int j = 0;
            for (; j + 1 < m; j += 2) {
                int s0 = __shfl_sync(0xffffffffu, md.x, j);
                float c0 = __int_as_float(__shfl_sync(0xffffffffu, md.y, j));
                int s1 = __shfl_sync(0xffffffffu, md.x, j + 1);
                float c1 = __int_as_float(__shfl_sync(0xffffffffu, md.y, j + 1));
                float4 h0 = __ldg((const float4*)(H + (size_t)s0 * D) + lane);
                float4 h1 = __ldg((const float4*)(H + (size_t)s1 * D) + lane);
                acc.x = fmaf(c0, h0.x, fmaf(c1, h1.x, acc.x));
                acc.y = fmaf(c0, h0.y, fmaf(c1, h1.y, acc.y));
                acc.z = fmaf(c0, h0.z, fmaf(c1, h1.z, acc.z));
                acc.w = fmaf(c0, h0.w, fmaf(c1, h1.w, acc.w));
            }
            if (j < m) {
                int s0 = __shfl_sync(0xffffffffu, md.x, j);
                float c0 = __int_as_float(__shfl_sync(0xffffffffu, md.y, j));
                float4 h0 = __ldg((const float4*)(H + (size_t)s0 * D) + lane);
                acc.x = fmaf(c0, h0.x, acc.x);
                acc.y = fmaf(c0, h0.y, acc.y);
                acc.z = fmaf(c0, h0.z, acc.z);
                acc.w = fmaf(c0, h0.w, acc.w);
            }
        }
    }
    float4 o = make_float4(fmaxf(acc.x, 0.f), fmaxf(acc.y, 0.f),
                           fmaxf(acc.z, 0.f), fmaxf(acc.w, 0.f));
    *(float4*)(out + (size_t)row * D + lane * 4) = o;
}

extern "C" void kernel_launch(void* const* d_in, const int* in_sizes, int n_in,
                              void* d_out, int out_size) {
    const float* h_word  = (const float*)d_in[0];
    const float* h_topic = (const float*)d_in[1];
    const float* W_ww = (const float*)d_in[3];
    const float* b_ww = (const float*)d_in[4];
    const float* W_wt = (const float*)d_in[5];
    const float* b_wt = (const float*)d_in[6];
    const float* W_wd = (const float*)d_in[7];
    const float* b_wd = (const float*)d_in[8];
    const float* W_td = (const float*)d_in[9];
    const float* b_td = (const float*)d_in[10];
    const float* W_tt = (const float*)d_in[11];
    const float* b_tt = (const float*)d_in[12];
    const int*   src_ww = (const int*)d_in[13];
    const int*   dst_ww = (const int*)d_in[14];
    const float* ew_ww  = (const float*)d_in[15];
    const int*   src_wt = (const int*)d_in[16];
    const int*   dst_wt = (const int*)d_in[17];
    const float* ew_wt  = (const float*)d_in[18];
    const int*   src_wd = (const int*)d_in[19];
    const int*   dst_wd = (const int*)d_in[20];
    const float* ew_wd  = (const float*)d_in[21];
    const int*   src_td = (const int*)d_in[22];
    const int*   dst_td = (const int*)d_in[23];
    const float* ew_td  = (const float*)d_in[24];
    const int*   src_tt = (const int*)d_in[25];
    const int*   dst_tt = (const int*)d_in[26];
    const float* ew_tt  = (const float*)d_in[27];

    const int E_ww = in_sizes[13];
    const int E_wt = in_sizes[16];
    const int E_wd = in_sizes[19];
    const int E_td = in_sizes[22];
    const int E_tt = in_sizes[25];

    float* out = (float*)d_out;

    float *H, *rcnt;
    int *cnt, *offs, *cursor, *bsum;
    int2* perm;
    cudaGetSymbolAddress((void**)&H, g_h);
    cudaGetSymbolAddress((void**)&cnt, g_cnt);
    cudaGetSymbolAddress((void**)&offs, g_offs);
    cudaGetSymbolAddress((void**)&cursor, g_cursor);
    cudaGetSymbolAddress((void**)&rcnt, g_rcnt);
    cudaGetSymbolAddress((void**)&bsum, g_bsum);
    cudaGetSymbolAddress((void**)&perm, g_perm);

    const int vb_ww = 0;
    const int vb_wt = NW;
    const int vb_tt = NW + NT;
    const int vb_wd = NW + 2 * NT;
    const int vb_td = NW + 2 * NT + ND;

    // fork/join resources: created fresh per call (kernel_launch runs ~2x;
    // destroying streams mid-capture is illegal, so they are leaked on purpose)
    cudaStream_t s2;
    cudaEvent_t evFork, evJoin;
    cudaStreamCreateWithFlags(&s2, cudaStreamNonBlocking);
    cudaEventCreateWithFlags(&evFork, cudaEventDisableTiming);
    cudaEventCreateWithFlags(&evJoin, cudaEventDisableTiming);

    // fork: side stream runs the GEMM chain
    cudaEventRecord(evFork, 0);
    cudaStreamWaitEvent(s2, evFork, 0);

    // ---- side stream: compose -> GEMM ----
    {
        const int csm = (128 * 129 + 128) * (int)sizeof(float);
        cudaFuncSetAttribute(compose1, cudaFuncAttributeMaxDynamicSharedMemorySize, csm);
        cudaFuncSetAttribute(compose2, cudaFuncAttributeMaxDynamicSharedMemorySize, csm);
        compose1<<<258, 128, csm, s2>>>(W_ww, W_wt, b_ww, b_wt, W_td, W_tt, b_td, b_tt);
        compose2<<<129, 128, csm, s2>>>(W_wd, b_wd);
        const int smem_bytes = 139264;
        cudaFuncSetAttribute(gemm_mma, cudaFuncAttributeMaxDynamicSharedMemorySize,
                             smem_bytes);
        gemm_mma<<<TILES_W + TILES_T, 256, smem_bytes, s2>>>(h_word, h_topic, H);
        cudaEventRecord(evJoin, s2);
    }

    // ---- main stream: CSR build chain ----
    cudaMemsetAsync(cnt, 0, NV * sizeof(int), 0);
    {
        Cnt4Args ca;
        ca.dst4[0] = (const int4*)dst_ww; ca.vbase[0] = vb_ww;
        ca.dst4[1] = (const int4*)dst_wt; ca.vbase[1] = vb_wt;
        ca.dst4[2] = (const int4*)dst_tt; ca.vbase[2] = vb_tt;
        ca.dst4[3] = (const int4*)dst_wd; ca.vbase[3] = vb_wd;
        ca.dst4[4] = (const int4*)dst_td; ca.vbase[4] = vb_td;
        ca.cum4[0] = 0;
        ca.cum4[1] = E_ww / 4;
        ca.cum4[2] = ca.cum4[1] + E_wt / 4;
        ca.cum4[3] = ca.cum4[2] + E_tt / 4;
        ca.cum4[4] = ca.cum4[3] + E_wd / 4;
        ca.cum4[5] = ca.cum4[4] + E_td / 4;
        count_all<<<(ca.cum4[5] + 255) / 256, 256>>>(ca, cnt);
    }
    scanA<<<SCAN_BLK, 1024>>>(cnt, NV, offs, rcnt, bsum);
    scanC<<<SCAN_BLK, 1024>>>(offs, NV, bsum, cursor);
    {
        FillArgs fa;
        fa.src[0] = src_ww; fa.dst[0] = dst_ww; fa.ew[0] = ew_ww; fa.vbase[0] = vb_ww; fa.soff[0] = 0;
        fa.src[1] = src_wt; fa.dst[1] = dst_wt; fa.ew[1] = ew_wt; fa.vbase[1] = vb_wt; fa.soff[1] = 0;
        fa.src[2] = src_tt; fa.dst[2] = dst_tt; fa.ew[2] = ew_tt; fa.vbase[2] = vb_tt; fa.soff[2] = NW;
        fa.src[3] = src_wd; fa.dst[3] = dst_wd; fa.ew[3] = ew_wd; fa.vbase[3] = vb_wd; fa.soff[3] = 0;
        fa.src[4] = src_td; fa.dst[4] = dst_td; fa.ew[4] = ew_td; fa.vbase[4] = vb_td; fa.soff[4] = NW;
        fa.cum[0] = 0;
        fa.cum[1] = E_ww;
        fa.cum[2] = fa.cum[1] + E_wt;
        fa.cum[3] = fa.cum[2] + E_tt;
        fa.cum[4] = fa.cum[3] + E_wd;
        fa.cum[5] = fa.cum[4] + E_td;
        fill_kernel<<<(fa.cum[5] + 255) / 256, 256>>>(fa, rcnt, cursor, perm);
    }

    // join: gather needs both H (side) and CSR (main)
    cudaStreamWaitEvent(0, evJoin, 0);
    gather_kernel<<<(NROW * 32 + 255) / 256, 256>>>(perm, offs, cnt, H, out);
}